// round 1
// baseline (speedup 1.0000x reference)
#include <cuda_runtime.h>
#include <math.h>

// Problem constants: N=512, H=64, M=1024, B=256, ETA=1
#define L2E 1.4426950408889634f

// Scratch (static __device__ arrays: allowed; no runtime allocation)
__device__ float  g_Bn[64 * 512];          // softmax(B_logits)          (H,N)
__device__ float  g_phiT[64 * 1024];       // phi_mu transposed          (H,M)
__device__ float  g_plusT[512 * 1024];     // (memory[:,n] > 0) as float (N,M)
__device__ float  g_rmax[511 * 64];        // per-(n,h) row max of masked A_logits
__device__ float  g_rinvZ[511 * 64];       // per-(n,h) 1/sum(exp)
__device__ float  g_hat[511 * 256 * 64];   // hat_phi laid out (n, b, h)
__device__ double g_acc;                   // global BCE accumulator

__global__ void k_zero() { g_acc = 0.0; }

// ---------------------------------------------------------------------------
// Bn = softmax(B_logits, axis=-1). One warp per h.
__global__ void k_bn(const float* __restrict__ Blog) {
    int h = blockIdx.x, l = threadIdx.x;
    const float* row = Blog + h * 512;
    float x[16];
    float mx = -3.402823466e38f;
#pragma unroll
    for (int k = 0; k < 16; k++) { x[k] = row[l + k * 32]; mx = fmaxf(mx, x[k]); }
#pragma unroll
    for (int o = 16; o; o >>= 1) mx = fmaxf(mx, __shfl_xor_sync(0xffffffffu, mx, o));
    float s = 0.f;
#pragma unroll
    for (int k = 0; k < 16; k++) { x[k] = exp2f((x[k] - mx) * L2E); s += x[k]; }
#pragma unroll
    for (int o = 16; o; o >>= 1) s += __shfl_xor_sync(0xffffffffu, s, o);
    float inv = 1.0f / s;
#pragma unroll
    for (int k = 0; k < 16; k++) g_Bn[h * 512 + l + k * 32] = x[k] * inv;
}

// ---------------------------------------------------------------------------
// phiT[h][m] = sum_n Bn[h][n] * memory[m][n].  One block per m.
__global__ void k_phi(const float* __restrict__ mem) {
    __shared__ float row[512];
    int m = blockIdx.x, tid = threadIdx.x;
    for (int i = tid; i < 512; i += 128) row[i] = mem[m * 512 + i];
    __syncthreads();
    int w = tid >> 5, l = tid & 31;
#pragma unroll 4
    for (int hh = 0; hh < 16; hh++) {
        int h = w * 16 + hh;
        float a = 0.f;
#pragma unroll
        for (int k = 0; k < 16; k++) { int i = l + k * 32; a += g_Bn[h * 512 + i] * row[i]; }
#pragma unroll
        for (int o = 16; o; o >>= 1) a += __shfl_xor_sync(0xffffffffu, a, o);
        if (l == 0) g_phiT[h * 1024 + m] = a;
    }
}

// ---------------------------------------------------------------------------
// plusT[n][m] = memory[m][n] > 0
__global__ void k_plus(const float* __restrict__ mem) {
    int idx = blockIdx.x * 256 + threadIdx.x;
    int n = idx >> 10, m = idx & 1023;
    g_plusT[idx] = (mem[m * 512 + n] > 0.0f) ? 1.0f : 0.0f;
}

// ---------------------------------------------------------------------------
// Per-row (n_pos in 1..511, h in 0..63) masked-softmax stats over i < n_pos.
// row r = (n_pos-1)*64 + h ; logits row = A_logits[(n_pos*64 + h)*512 + i]
__global__ void k_rowstats(const float* __restrict__ Alog) {
    int w = threadIdx.x >> 5, l = threadIdx.x & 31;
    int r = blockIdx.x * 8 + w;                  // 0..32703
    int n_pos = (r >> 6) + 1;
    const float* row = Alog + (size_t)(r + 64) * 512;
    float x[16];
    float mx = -3.402823466e38f;
#pragma unroll
    for (int k = 0; k < 16; k++) {
        int i = l + k * 32;
        x[k] = row[i];
        if (i < n_pos) mx = fmaxf(mx, x[k]);
    }
#pragma unroll
    for (int o = 16; o; o >>= 1) mx = fmaxf(mx, __shfl_xor_sync(0xffffffffu, mx, o));
    float s = 0.f;
#pragma unroll
    for (int k = 0; k < 16; k++) {
        int i = l + k * 32;
        if (i < n_pos) s += exp2f((x[k] - mx) * L2E);
    }
#pragma unroll
    for (int o = 16; o; o >>= 1) s += __shfl_xor_sync(0xffffffffu, s, o);
    if (l == 0) { g_rmax[r] = mx; g_rinvZ[r] = 1.0f / s; }
}

// ---------------------------------------------------------------------------
// hat[n][b][h] = sum_{i<n} softmax(A_logits[n,h,:n])[i] * seq[b][i]
// One block per n (reversed for load balance). Tile: 64h x 256b, K chunks of 32.
// Softmax weights computed on the fly from (rmax, rinvZ); chunks with i >= n skipped.
__global__ void __launch_bounds__(256, 2) k_hat(const float* __restrict__ Alog,
                                                const float* __restrict__ seq) {
    int n_idx = 510 - blockIdx.x;
    int n_pos = n_idx + 1;
    __shared__ float As[32 * 65];      // As[i_local][h], pad 65 (conflict-free)
    __shared__ float Ss[32 * 257];     // Ss[i_local][b], pad 257
    __shared__ float rmax_s[64], rinv_s[64];
    int tid = threadIdx.x;
    if (tid < 64) {
        rmax_s[tid] = g_rmax[n_idx * 64 + tid];
        rinv_s[tid] = g_rinvZ[n_idx * 64 + tid];
    }
    float acc[4][16];
#pragma unroll
    for (int j = 0; j < 4; j++)
#pragma unroll
        for (int q = 0; q < 16; q++) acc[j][q] = 0.f;

    int thx = tid & 15;   // b group
    int thy = tid >> 4;   // h group
    int nchunks = (n_pos + 31) >> 5;
    __syncthreads();

    for (int kc = 0; kc < nchunks; kc++) {
        int i0 = kc * 32;
        // A tile: 64h x 32i, softmax weight applied on load
#pragma unroll
        for (int p = 0; p < 8; p++) {
            int h = (tid >> 5) + p * 8;
            int il = tid & 31;
            int i = i0 + il;
            float v = Alog[((size_t)(n_pos * 64 + h)) * 512 + i];
            float wv = (i < n_pos) ? exp2f((v - rmax_s[h]) * L2E) * rinv_s[h] : 0.f;
            As[il * 65 + h] = wv;
        }
        // seq tile: 256b x 32i
#pragma unroll
        for (int p = 0; p < 32; p++) {
            int e = p * 256 + tid;
            int il = e & 31;
            int b = e >> 5;
            Ss[il * 257 + b] = seq[b * 512 + i0 + il];
        }
        __syncthreads();
#pragma unroll 8
        for (int k = 0; k < 32; k++) {
            float a0 = As[k * 65 + thy * 4 + 0];
            float a1 = As[k * 65 + thy * 4 + 1];
            float a2 = As[k * 65 + thy * 4 + 2];
            float a3 = As[k * 65 + thy * 4 + 3];
#pragma unroll
            for (int q = 0; q < 4; q++) {
#pragma unroll
                for (int d = 0; d < 4; d++) {
                    float sv = Ss[k * 257 + thx * 4 + q * 64 + d];
                    acc[0][q * 4 + d] += a0 * sv;
                    acc[1][q * 4 + d] += a1 * sv;
                    acc[2][q * 4 + d] += a2 * sv;
                    acc[3][q * 4 + d] += a3 * sv;
                }
            }
        }
        __syncthreads();
    }
    // write hat[(n*256 + b)*64 + h], 4 h contiguous per store
#pragma unroll
    for (int q = 0; q < 4; q++) {
#pragma unroll
        for (int d = 0; d < 4; d++) {
            int b = thx * 4 + q * 64 + d;
            float4 v = make_float4(acc[0][q * 4 + d], acc[1][q * 4 + d],
                                   acc[2][q * 4 + d], acc[3][q * 4 + d]);
            *(float4*)&g_hat[(size_t)(n_idx * 256 + b) * 64 + thy * 4] = v;
        }
    }
}

// ---------------------------------------------------------------------------
// Fused score GEMM + softmax retrieval + BCE.
// Block = (btile, n): 32 b-rows x M=1024, K=64. phi chunked 128 m through smem.
// |score| <= 64 so no max-subtraction needed.
__global__ void __launch_bounds__(256, 2) k_score(const float* __restrict__ seq) {
    int btile = blockIdx.x;           // 0..7  -> 32 b each
    int n_idx = blockIdx.y;           // 0..510
    int n_pos = n_idx + 1;
    __shared__ float hat_s[32 * 65];  // hat_s[row][h]
    __shared__ float phi_s[64 * 129]; // phi_s[h][m_local]
    __shared__ float red[16];
    int tid = threadIdx.x;

    const float* hbase = g_hat + (size_t)(n_idx * 256 + btile * 32) * 64;
#pragma unroll
    for (int p = 0; p < 8; p++) {
        int e = p * 256 + tid;
        int r = e >> 6, h = e & 63;
        hat_s[r * 65 + h] = hbase[e];
    }

    int c = tid & 15;    // m lane
    int r2 = tid >> 4;   // row pair id: rows 2*r2, 2*r2+1
    float num0 = 0.f, den0 = 0.f, num1 = 0.f, den1 = 0.f;
    int ro0 = (2 * r2) * 65, ro1 = ro0 + 65;

    for (int mc = 0; mc < 8; mc++) {
        __syncthreads();  // protect hat_s (first iter) / phi_s (later iters)
#pragma unroll
        for (int p = 0; p < 32; p++) {
            int e = p * 256 + tid;
            int m = e & 127, h = e >> 7;
            phi_s[h * 129 + m] = g_phiT[h * 1024 + mc * 128 + m];
        }
        __syncthreads();

        float a0[8], a1[8];
#pragma unroll
        for (int j = 0; j < 8; j++) { a0[j] = 0.f; a1[j] = 0.f; }
#pragma unroll 8
        for (int h = 0; h < 64; h++) {
            float h0 = hat_s[ro0 + h];
            float h1 = hat_s[ro1 + h];
            const float* pr = &phi_s[h * 129 + c];
#pragma unroll
            for (int j = 0; j < 8; j++) {
                float pv = pr[j * 16];
                a0[j] += h0 * pv;
                a1[j] += h1 * pv;
            }
        }
#pragma unroll
        for (int j = 0; j < 8; j++) {
            int m = mc * 128 + c + j * 16;
            float pl = g_plusT[n_pos * 1024 + m];
            float e0 = expf(a0[j]);
            float e1 = expf(a1[j]);
            den0 += e0; num0 += e0 * pl;
            den1 += e1; num1 += e1 * pl;
        }
    }
    // reduce over the 16 m-lanes of each row
#pragma unroll
    for (int o = 8; o; o >>= 1) {
        num0 += __shfl_xor_sync(0xffffffffu, num0, o);
        den0 += __shfl_xor_sync(0xffffffffu, den0, o);
        num1 += __shfl_xor_sync(0xffffffffu, num1, o);
        den1 += __shfl_xor_sync(0xffffffffu, den1, o);
    }
    if (c == 0) {
        float local = 0.f;
#pragma unroll
        for (int rr = 0; rr < 2; rr++) {
            int b = btile * 32 + r2 * 2 + rr;
            float num = rr ? num1 : num0;
            float den = rr ? den1 : den0;
            float prob = num / den;
            prob = fminf(fmaxf(prob, 1e-6f), 1.0f - 1e-6f);
            bool t = seq[b * 512 + n_pos] > 0.0f;
            local += t ? -logf(prob) : -log1pf(-prob);
        }
        red[r2] = local;
    }
    __syncthreads();
    if (tid == 0) {
        double s = 0.0;
#pragma unroll
        for (int i = 0; i < 16; i++) s += (double)red[i];
        atomicAdd(&g_acc, s);
    }
}

__global__ void k_final(float* out) {
    out[0] = (float)(g_acc * (1.0 / (256.0 * 511.0)));
}

// ---------------------------------------------------------------------------
extern "C" void kernel_launch(void* const* d_in, const int* in_sizes, int n_in,
                              void* d_out, int out_size) {
    const float *seq = 0, *mem = 0, *Al = 0, *Bl = 0;
    for (int i = 0; i < n_in; i++) {
        switch (in_sizes[i]) {
            case 131072:   seq = (const float*)d_in[i]; break;  // (256,512)
            case 524288:   mem = (const float*)d_in[i]; break;  // (1024,512)
            case 16777216: Al  = (const float*)d_in[i]; break;  // (512,64,512)
            case 32768:    Bl  = (const float*)d_in[i]; break;  // (64,512)
        }
    }
    if (!seq) seq = (const float*)d_in[0];
    if (!mem) mem = (const float*)d_in[1];
    if (!Al)  Al  = (const float*)d_in[2];
    if (!Bl)  Bl  = (const float*)d_in[3];

    k_zero<<<1, 1>>>();
    k_bn<<<64, 32>>>(Bl);
    k_phi<<<1024, 128>>>(mem);
    k_plus<<<2048, 256>>>(mem);
    k_rowstats<<<4088, 256>>>(Al);
    k_hat<<<511, 256>>>(Al, seq);
    k_score<<<dim3(8, 511), 256>>>(seq);
    k_final<<<1, 1>>>((float*)d_out);
}

// round 3
// speedup vs baseline: 2.3798x; 2.3798x over previous
#include <cuda_runtime.h>
#include <cuda_bf16.h>
#include <math.h>
#include <stdint.h>

// Problem constants: N=512, H=64, M=1024, B=256, ETA=1
#define L2E 1.4426950408889634f

// ---------------------------------------------------------------------------
__device__ __forceinline__ uint32_t smem_u32(const void* p) {
    uint32_t a;
    asm("{ .reg .u64 t; cvta.to.shared.u64 t, %1; cvt.u32.u64 %0, t; }" : "=r"(a) : "l"(p));
    return a;
}
__device__ __forceinline__ void ldsm_x4(uint32_t r[4], uint32_t addr) {
    asm volatile("ldmatrix.sync.aligned.m8n8.x4.shared.b16 {%0,%1,%2,%3}, [%4];"
                 : "=r"(r[0]), "=r"(r[1]), "=r"(r[2]), "=r"(r[3]) : "r"(addr));
}
__device__ __forceinline__ void ldsm_x4t(uint32_t r[4], uint32_t addr) {
    asm volatile("ldmatrix.sync.aligned.m8n8.x4.trans.shared.b16 {%0,%1,%2,%3}, [%4];"
                 : "=r"(r[0]), "=r"(r[1]), "=r"(r[2]), "=r"(r[3]) : "r"(addr));
}
__device__ __forceinline__ void mma_bf16(float c[4], const uint32_t a[4],
                                         uint32_t b0, uint32_t b1) {
    asm volatile("mma.sync.aligned.m16n8k16.row.col.f32.bf16.bf16.f32 "
                 "{%0,%1,%2,%3}, {%4,%5,%6,%7}, {%8,%9}, {%0,%1,%2,%3};"
                 : "+f"(c[0]), "+f"(c[1]), "+f"(c[2]), "+f"(c[3])
                 : "r"(a[0]), "r"(a[1]), "r"(a[2]), "r"(a[3]), "r"(b0), "r"(b1));
}

// ---------------------------------------------------------------------------
// Scratch
__device__ float  g_Bn[64 * 512];
__device__ float  g_plusT[512 * 1024];
__device__ float  g_rmax[511 * 64];
__device__ float  g_rinvZ[511 * 64];
__device__ __align__(16) __nv_bfloat16 g_hatH[511 * 256 * 64];  // hi(hat) [n*256+b][h]
__device__ __align__(16) __nv_bfloat16 g_hatL[511 * 256 * 64];  // lo(hat)
__device__ __align__(16) __nv_bfloat16 g_phiTH[64 * 1024];      // hi(phi) [h][m]
__device__ __align__(16) __nv_bfloat16 g_phiTL[64 * 1024];      // lo(phi)
__device__ double g_acc;

__global__ void k_zero() { g_acc = 0.0; }

// ---------------------------------------------------------------------------
__global__ void k_bn(const float* __restrict__ Blog) {
    int h = blockIdx.x, l = threadIdx.x;
    const float* row = Blog + h * 512;
    float x[16];
    float mx = -3.402823466e38f;
#pragma unroll
    for (int k = 0; k < 16; k++) { x[k] = row[l + k * 32]; mx = fmaxf(mx, x[k]); }
#pragma unroll
    for (int o = 16; o; o >>= 1) mx = fmaxf(mx, __shfl_xor_sync(0xffffffffu, mx, o));
    float s = 0.f;
#pragma unroll
    for (int k = 0; k < 16; k++) { x[k] = exp2f((x[k] - mx) * L2E); s += x[k]; }
#pragma unroll
    for (int o = 16; o; o >>= 1) s += __shfl_xor_sync(0xffffffffu, s, o);
    float inv = 1.0f / s;
#pragma unroll
    for (int k = 0; k < 16; k++) g_Bn[h * 512 + l + k * 32] = x[k] * inv;
}

// phi[h][m] = sum_n Bn[h][n] * memory[m][n], bf16 hi/lo, [h][m] layout
__global__ void k_phi(const float* __restrict__ mem) {
    __shared__ float row[512];
    int m = blockIdx.x, tid = threadIdx.x;
    for (int i = tid; i < 512; i += 128) row[i] = mem[m * 512 + i];
    __syncthreads();
    int w = tid >> 5, l = tid & 31;
#pragma unroll 4
    for (int hh = 0; hh < 16; hh++) {
        int h = w * 16 + hh;
        float a = 0.f;
#pragma unroll
        for (int k = 0; k < 16; k++) { int i = l + k * 32; a += g_Bn[h * 512 + i] * row[i]; }
#pragma unroll
        for (int o = 16; o; o >>= 1) a += __shfl_xor_sync(0xffffffffu, a, o);
        if (l == 0) {
            __nv_bfloat16 hi = __float2bfloat16(a);
            g_phiTH[h * 1024 + m] = hi;
            g_phiTL[h * 1024 + m] = __float2bfloat16(a - __bfloat162float(hi));
        }
    }
}

__global__ void k_plus(const float* __restrict__ mem) {
    int idx = blockIdx.x * 256 + threadIdx.x;
    int n = idx >> 10, m = idx & 1023;
    g_plusT[idx] = (mem[m * 512 + n] > 0.0f) ? 1.0f : 0.0f;
}

// ---------------------------------------------------------------------------
__global__ void k_rowstats(const float* __restrict__ Alog) {
    int w = threadIdx.x >> 5, l = threadIdx.x & 31;
    int r = blockIdx.x * 8 + w;
    int n_pos = (r >> 6) + 1;
    const float* row = Alog + (size_t)(r + 64) * 512;
    float x[16];
    float mx = -3.402823466e38f;
#pragma unroll
    for (int k = 0; k < 16; k++) {
        int i = l + k * 32;
        x[k] = row[i];
        if (i < n_pos) mx = fmaxf(mx, x[k]);
    }
#pragma unroll
    for (int o = 16; o; o >>= 1) mx = fmaxf(mx, __shfl_xor_sync(0xffffffffu, mx, o));
    float s = 0.f;
#pragma unroll
    for (int k = 0; k < 16; k++) {
        int i = l + k * 32;
        if (i < n_pos) s += exp2f((x[k] - mx) * L2E);
    }
#pragma unroll
    for (int o = 16; o; o >>= 1) s += __shfl_xor_sync(0xffffffffu, s, o);
    if (l == 0) { g_rmax[r] = mx; g_rinvZ[r] = 1.0f / s; }
}

// ---------------------------------------------------------------------------
// hat[n][b][h] -> bf16 hi/lo (FFMA path, unchanged logic from R1)
__global__ void __launch_bounds__(256, 2) k_hat(const float* __restrict__ Alog,
                                                const float* __restrict__ seq) {
    int n_idx = 510 - blockIdx.x;
    int n_pos = n_idx + 1;
    __shared__ float As[32 * 65];
    __shared__ float Ss[32 * 257];
    __shared__ float rmax_s[64], rinv_s[64];
    int tid = threadIdx.x;
    if (tid < 64) {
        rmax_s[tid] = g_rmax[n_idx * 64 + tid];
        rinv_s[tid] = g_rinvZ[n_idx * 64 + tid];
    }
    float acc[4][16];
#pragma unroll
    for (int j = 0; j < 4; j++)
#pragma unroll
        for (int q = 0; q < 16; q++) acc[j][q] = 0.f;

    int thx = tid & 15;
    int thy = tid >> 4;
    int nchunks = (n_pos + 31) >> 5;
    __syncthreads();

    for (int kc = 0; kc < nchunks; kc++) {
        int i0 = kc * 32;
#pragma unroll
        for (int p = 0; p < 8; p++) {
            int h = (tid >> 5) + p * 8;
            int il = tid & 31;
            int i = i0 + il;
            float v = Alog[((size_t)(n_pos * 64 + h)) * 512 + i];
            float wv = (i < n_pos) ? exp2f((v - rmax_s[h]) * L2E) * rinv_s[h] : 0.f;
            As[il * 65 + h] = wv;
        }
#pragma unroll
        for (int p = 0; p < 32; p++) {
            int e = p * 256 + tid;
            int il = e & 31;
            int b = e >> 5;
            Ss[il * 257 + b] = seq[b * 512 + i0 + il];
        }
        __syncthreads();
#pragma unroll 8
        for (int k = 0; k < 32; k++) {
            float a0 = As[k * 65 + thy * 4 + 0];
            float a1 = As[k * 65 + thy * 4 + 1];
            float a2 = As[k * 65 + thy * 4 + 2];
            float a3 = As[k * 65 + thy * 4 + 3];
#pragma unroll
            for (int q = 0; q < 4; q++) {
#pragma unroll
                for (int d = 0; d < 4; d++) {
                    float sv = Ss[k * 257 + thx * 4 + q * 64 + d];
                    acc[0][q * 4 + d] += a0 * sv;
                    acc[1][q * 4 + d] += a1 * sv;
                    acc[2][q * 4 + d] += a2 * sv;
                    acc[3][q * 4 + d] += a3 * sv;
                }
            }
        }
        __syncthreads();
    }
#pragma unroll
    for (int q = 0; q < 4; q++) {
#pragma unroll
        for (int d = 0; d < 4; d++) {
            int b = thx * 4 + q * 64 + d;
            size_t base = (size_t)(n_idx * 256 + b) * 64 + thy * 4;
            float v[4] = { acc[0][q * 4 + d], acc[1][q * 4 + d],
                           acc[2][q * 4 + d], acc[3][q * 4 + d] };
            __nv_bfloat16 hi[4], lo[4];
#pragma unroll
            for (int j = 0; j < 4; j++) {
                hi[j] = __float2bfloat16(v[j]);
                lo[j] = __float2bfloat16(v[j] - __bfloat162float(hi[j]));
            }
            __nv_bfloat162 t;
            t.x = hi[0]; t.y = hi[1]; *(__nv_bfloat162*)&g_hatH[base] = t;
            t.x = hi[2]; t.y = hi[3]; *(__nv_bfloat162*)&g_hatH[base + 2] = t;
            t.x = lo[0]; t.y = lo[1]; *(__nv_bfloat162*)&g_hatL[base] = t;
            t.x = lo[2]; t.y = lo[3]; *(__nv_bfloat162*)&g_hatL[base + 2] = t;
        }
    }
}

// ---------------------------------------------------------------------------
// Fused score GEMM (mma.sync bf16 hi/lo) + softmax retrieval + BCE.
// Block = (n, btile of 128 b). smem: hat[b][h] (pitch 144B), phi chunk [h][m]
// (pitch 528B, 256 m per chunk). Warp w owns b-rows [w*16, w*16+16), all m.
#define SM_RED   0
#define SM_HATH  256
#define SM_HATL  (SM_HATH + 128 * 144)
#define SM_PHIH  (SM_HATL + 128 * 144)
#define SM_PHIL  (SM_PHIH + 64 * 528)
#define SM_TOTAL (SM_PHIL + 64 * 528)

__global__ void __launch_bounds__(256, 2) k_score_mma(const float* __restrict__ seq) {
    extern __shared__ char sm[];
    float* red = (float*)(sm + SM_RED);
    int tid = threadIdx.x, wid = tid >> 5, ln = tid & 31;
    int n_idx = blockIdx.x, n_pos = n_idx + 1, btile = blockIdx.y;

    uint32_t hatH32 = smem_u32(sm + SM_HATH);
    uint32_t hatL32 = smem_u32(sm + SM_HATL);
    uint32_t phiH32 = smem_u32(sm + SM_PHIH);
    uint32_t phiL32 = smem_u32(sm + SM_PHIL);

    // stage hat tile: 128 rows x 64 bf16 (128B) -> pitch 144B
    {
        size_t row0 = (size_t)(n_idx * 256 + btile * 128);
        const uint4* gH = (const uint4*)(g_hatH + row0 * 64);
        const uint4* gL = (const uint4*)(g_hatL + row0 * 64);
#pragma unroll
        for (int it = 0; it < 4; it++) {
            int idx = it * 256 + tid;
            int r = idx >> 3, q = idx & 7;
            *(uint4*)(sm + SM_HATH + r * 144 + q * 16) = gH[r * 8 + q];
            *(uint4*)(sm + SM_HATL + r * 144 + q * 16) = gL[r * 8 + q];
        }
    }
    __syncthreads();

    // resident A frags: rows wid*16 .. +16, 4 k-steps, hi+lo
    uint32_t aH[4][4], aL[4][4];
    {
        uint32_t rb = wid * 16 + (ln & 15);
        uint32_t cb = ((ln >> 4) & 1) * 16;  // +8 elems = 16B
#pragma unroll
        for (int ks = 0; ks < 4; ks++) {
            uint32_t off = rb * 144 + ks * 32 + cb;
            ldsm_x4(aH[ks], hatH32 + off);
            ldsm_x4(aL[ks], hatL32 + off);
        }
    }

    float num0 = 0.f, den0 = 0.f, num1 = 0.f, den1 = 0.f;
    const float* plrow = g_plusT + n_pos * 1024;

    for (int c = 0; c < 4; c++) {
        __syncthreads();
        // stage phi chunk c: 64 rows x 256 bf16 (512B) -> pitch 528B
#pragma unroll
        for (int it = 0; it < 8; it++) {
            int idx = it * 256 + tid;
            int r = idx >> 5, q = idx & 31;
            *(uint4*)(sm + SM_PHIH + r * 528 + q * 16) =
                *(const uint4*)(g_phiTH + r * 1024 + c * 256 + q * 8);
            *(uint4*)(sm + SM_PHIL + r * 528 + q * 16) =
                *(const uint4*)(g_phiTL + r * 1024 + c * 256 + q * 8);
        }
        __syncthreads();

        for (int pr = 0; pr < 16; pr++) {  // n8-tile pairs (16 m each)
            uint32_t bH[4][4], bL[4][4];
            {
                uint32_t rk = (ln & 15);
                uint32_t cm = pr * 16 + ((ln >> 4) & 1) * 8;
#pragma unroll
                for (int ks = 0; ks < 4; ks++) {
                    uint32_t off = (ks * 16 + rk) * 528 + cm * 2;
                    ldsm_x4t(bH[ks], phiH32 + off);
                    ldsm_x4t(bL[ks], phiL32 + off);
                }
            }
#pragma unroll
            for (int t2 = 0; t2 < 2; t2++) {
                float cc[4] = {0.f, 0.f, 0.f, 0.f};
#pragma unroll
                for (int ks = 0; ks < 4; ks++) {
                    mma_bf16(cc, aH[ks], bH[ks][t2 * 2], bH[ks][t2 * 2 + 1]);
                    mma_bf16(cc, aH[ks], bL[ks][t2 * 2], bL[ks][t2 * 2 + 1]);
                    mma_bf16(cc, aL[ks], bH[ks][t2 * 2], bH[ks][t2 * 2 + 1]);
                }
                int mb = c * 256 + pr * 16 + t2 * 8 + 2 * (ln & 3);
                float p0 = __ldg(plrow + mb);
                float p1 = __ldg(plrow + mb + 1);
                float e0 = __expf(cc[0]), e1 = __expf(cc[1]);
                float e2 = __expf(cc[2]), e3 = __expf(cc[3]);
                den0 += e0 + e1; num0 += e0 * p0 + e1 * p1;
                den1 += e2 + e3; num1 += e2 * p0 + e3 * p1;
            }
        }
    }

    // reduce over the 4 lanes sharing each row
#pragma unroll
    for (int o = 1; o <= 2; o <<= 1) {
        num0 += __shfl_xor_sync(0xffffffffu, num0, o);
        den0 += __shfl_xor_sync(0xffffffffu, den0, o);
        num1 += __shfl_xor_sync(0xffffffffu, num1, o);
        den1 += __shfl_xor_sync(0xffffffffu, den1, o);
    }
    if ((ln & 3) == 0) {
        int r = ln >> 2;
        int b0 = btile * 128 + wid * 16 + r;
        int b1 = b0 + 8;
        float pr0 = fminf(fmaxf(num0 / den0, 1e-6f), 1.0f - 1e-6f);
        float pr1 = fminf(fmaxf(num1 / den1, 1e-6f), 1.0f - 1e-6f);
        bool t0 = seq[b0 * 512 + n_pos] > 0.0f;
        bool t1 = seq[b1 * 512 + n_pos] > 0.0f;
        float bce = (t0 ? -logf(pr0) : -log1pf(-pr0)) +
                    (t1 ? -logf(pr1) : -log1pf(-pr1));
        red[wid * 8 + r] = bce;
    }
    __syncthreads();
    if (tid == 0) {
        double s = 0.0;
#pragma unroll
        for (int i = 0; i < 64; i++) s += (double)red[i];
        atomicAdd(&g_acc, s);
    }
}

__global__ void k_final(float* out) {
    out[0] = (float)(g_acc * (1.0 / (256.0 * 511.0)));
}

// ---------------------------------------------------------------------------
extern "C" void kernel_launch(void* const* d_in, const int* in_sizes, int n_in,
                              void* d_out, int out_size) {
    const float *seq = 0, *mem = 0, *Al = 0, *Bl = 0;
    for (int i = 0; i < n_in; i++) {
        switch (in_sizes[i]) {
            case 131072:   seq = (const float*)d_in[i]; break;  // (256,512)
            case 524288:   mem = (const float*)d_in[i]; break;  // (1024,512)
            case 16777216: Al  = (const float*)d_in[i]; break;  // (512,64,512)
            case 32768:    Bl  = (const float*)d_in[i]; break;  // (64,512)
        }
    }
    if (!seq) seq = (const float*)d_in[0];
    if (!mem) mem = (const float*)d_in[1];
    if (!Al)  Al  = (const float*)d_in[2];
    if (!Bl)  Bl  = (const float*)d_in[3];

    cudaFuncSetAttribute(k_score_mma, cudaFuncAttributeMaxDynamicSharedMemorySize, SM_TOTAL);

    k_zero<<<1, 1>>>();
    k_bn<<<64, 32>>>(Bl);
    k_phi<<<1024, 128>>>(mem);
    k_plus<<<2048, 256>>>(mem);
    k_rowstats<<<4088, 256>>>(Al);
    k_hat<<<511, 256>>>(Al, seq);
    k_score_mma<<<dim3(511, 2), 256, SM_TOTAL>>>(seq);
    k_final<<<1, 1>>>((float*)d_out);
}

// round 4
// speedup vs baseline: 3.5898x; 1.5085x over previous
#include <cuda_runtime.h>
#include <cuda_bf16.h>
#include <math.h>
#include <stdint.h>

// Problem constants: N=512, H=64, M=1024, B=256, ETA=1
#define L2E 1.4426950408889634f

// ---------------------------------------------------------------------------
__device__ __forceinline__ uint32_t smem_u32(const void* p) {
    uint32_t a;
    asm("{ .reg .u64 t; cvta.to.shared.u64 t, %1; cvt.u32.u64 %0, t; }" : "=r"(a) : "l"(p));
    return a;
}
__device__ __forceinline__ void ldsm_x4(uint32_t r[4], uint32_t addr) {
    asm volatile("ldmatrix.sync.aligned.m8n8.x4.shared.b16 {%0,%1,%2,%3}, [%4];"
                 : "=r"(r[0]), "=r"(r[1]), "=r"(r[2]), "=r"(r[3]) : "r"(addr));
}
__device__ __forceinline__ void ldsm_x4t(uint32_t r[4], uint32_t addr) {
    asm volatile("ldmatrix.sync.aligned.m8n8.x4.trans.shared.b16 {%0,%1,%2,%3}, [%4];"
                 : "=r"(r[0]), "=r"(r[1]), "=r"(r[2]), "=r"(r[3]) : "r"(addr));
}
__device__ __forceinline__ void mma_bf16(float c[4], const uint32_t a[4],
                                         uint32_t b0, uint32_t b1) {
    asm volatile("mma.sync.aligned.m16n8k16.row.col.f32.bf16.bf16.f32 "
                 "{%0,%1,%2,%3}, {%4,%5,%6,%7}, {%8,%9}, {%0,%1,%2,%3};"
                 : "+f"(c[0]), "+f"(c[1]), "+f"(c[2]), "+f"(c[3])
                 : "r"(a[0]), "r"(a[1]), "r"(a[2]), "r"(a[3]), "r"(b0), "r"(b1));
}
// pack two f32 -> bf16x2 (lo in low half)
__device__ __forceinline__ uint32_t packbf(float lo, float hi) {
    uint32_t d;
    asm("cvt.rn.bf16x2.f32 %0, %1, %2;" : "=r"(d) : "f"(hi), "f"(lo));
    return d;
}
// residual pack: lo-parts of (f0,f1) after removing bf16 hi p
__device__ __forceinline__ uint32_t packresid(uint32_t p, float f0, float f1) {
    float r0 = f0 - __uint_as_float(p << 16);
    float r1 = f1 - __uint_as_float(p & 0xffff0000u);
    return packbf(r0, r1);
}

// ---------------------------------------------------------------------------
// Scratch
__device__ float  g_Bn[64 * 512];
__device__ float  g_rmax[511 * 64];
__device__ float  g_rinvZ[511 * 64];
__device__ __align__(16) __nv_bfloat16 g_phiTH[64 * 1024];  // hi(phi) [h][m]
__device__ __align__(16) __nv_bfloat16 g_phiTL[64 * 1024];  // lo(phi)
__device__ double g_acc;

__global__ void k_zero() { g_acc = 0.0; }

// ---------------------------------------------------------------------------
__global__ void k_bn(const float* __restrict__ Blog) {
    int h = blockIdx.x, l = threadIdx.x;
    const float* row = Blog + h * 512;
    float x[16];
    float mx = -3.402823466e38f;
#pragma unroll
    for (int k = 0; k < 16; k++) { x[k] = row[l + k * 32]; mx = fmaxf(mx, x[k]); }
#pragma unroll
    for (int o = 16; o; o >>= 1) mx = fmaxf(mx, __shfl_xor_sync(0xffffffffu, mx, o));
    float s = 0.f;
#pragma unroll
    for (int k = 0; k < 16; k++) { x[k] = exp2f((x[k] - mx) * L2E); s += x[k]; }
#pragma unroll
    for (int o = 16; o; o >>= 1) s += __shfl_xor_sync(0xffffffffu, s, o);
    float inv = 1.0f / s;
#pragma unroll
    for (int k = 0; k < 16; k++) g_Bn[h * 512 + l + k * 32] = x[k] * inv;
}

// phi[h][m] = sum_n Bn[h][n] * memory[m][n], bf16 hi/lo, [h][m] layout
__global__ void k_phi(const float* __restrict__ mem) {
    __shared__ float row[512];
    int m = blockIdx.x, tid = threadIdx.x;
    for (int i = tid; i < 512; i += 128) row[i] = mem[m * 512 + i];
    __syncthreads();
    int w = tid >> 5, l = tid & 31;
#pragma unroll 4
    for (int hh = 0; hh < 16; hh++) {
        int h = w * 16 + hh;
        float a = 0.f;
#pragma unroll
        for (int k = 0; k < 16; k++) { int i = l + k * 32; a += g_Bn[h * 512 + i] * row[i]; }
#pragma unroll
        for (int o = 16; o; o >>= 1) a += __shfl_xor_sync(0xffffffffu, a, o);
        if (l == 0) {
            __nv_bfloat16 hi = __float2bfloat16(a);
            g_phiTH[h * 1024 + m] = hi;
            g_phiTL[h * 1024 + m] = __float2bfloat16(a - __bfloat162float(hi));
        }
    }
}

// ---------------------------------------------------------------------------
__global__ void k_rowstats(const float* __restrict__ Alog) {
    int w = threadIdx.x >> 5, l = threadIdx.x & 31;
    int r = blockIdx.x * 8 + w;
    int n_pos = (r >> 6) + 1;
    const float* row = Alog + (size_t)(r + 64) * 512;
    float x[16];
    float mx = -3.402823466e38f;
#pragma unroll
    for (int k = 0; k < 16; k++) {
        int i = l + k * 32;
        x[k] = row[i];
        if (i < n_pos) mx = fmaxf(mx, x[k]);
    }
#pragma unroll
    for (int o = 16; o; o >>= 1) mx = fmaxf(mx, __shfl_xor_sync(0xffffffffu, mx, o));
    float s = 0.f;
#pragma unroll
    for (int k = 0; k < 16; k++) {
        int i = l + k * 32;
        if (i < n_pos) s += exp2f((x[k] - mx) * L2E);
    }
#pragma unroll
    for (int o = 16; o; o >>= 1) s += __shfl_xor_sync(0xffffffffu, s, o);
    if (l == 0) { g_rmax[r] = mx; g_rinvZ[r] = 1.0f / s; }
}

// ---------------------------------------------------------------------------
// FUSED kernel: per n_pos: hat GEMM (tensor) -> register A-frag conversion ->
// score GEMM (tensor) -> softmax retrieval -> BCE.
// One CTA per n (511), 256 threads; warp w owns b-rows [w*32, w*32+32).
//
// smem map (bytes):
//   [0, 1024)        red (64 floats used)
//   [1024, 5120)     plus row (1024 f32)
//   [5120, 5632)     rmax/rinv (64+64 f32)
//   [5632, ...)      DYN region, two overlapping phases:
//     hat phase:  WH [32i][64h] bf16 pitch 144 (4608B), WL (+4608, 4608B),
//                 S  [256b][32i] bf16 pitch 80 (+9216, 20480B)
//     score phase: PHIH [64h][256m] bf16 pitch 528 (33792B), PHIL (+33792)
#define SM_RED   0
#define SM_PLUS  1024
#define SM_RMAX  5120
#define SM_DYN   5632
#define SM_WH    SM_DYN
#define SM_WL    (SM_DYN + 4608)
#define SM_S     (SM_DYN + 9216)
#define SM_PHIH  SM_DYN
#define SM_PHIL  (SM_DYN + 33792)
#define SM_TOTAL (SM_DYN + 67584)

__global__ void __launch_bounds__(256, 2) k_fused(const float* __restrict__ Alog,
                                                  const float* __restrict__ seq,
                                                  const float* __restrict__ mem) {
    extern __shared__ char sm[];
    int tid = threadIdx.x, wid = tid >> 5, ln = tid & 31;
    int n_idx = blockIdx.x, n_pos = n_idx + 1;

    float* red    = (float*)(sm + SM_RED);
    float* plus_s = (float*)(sm + SM_PLUS);
    float* rmax_s = (float*)(sm + SM_RMAX);
    float* rinv_s = rmax_s + 64;

    if (tid < 64) {
        rmax_s[tid] = g_rmax[n_idx * 64 + tid];
        rinv_s[tid] = g_rinvZ[n_idx * 64 + tid];
    }
#pragma unroll
    for (int q = 0; q < 4; q++) {
        int m = q * 256 + tid;
        plus_s[m] = (mem[(size_t)m * 512 + n_pos] > 0.0f) ? 1.0f : 0.0f;
    }

    uint32_t s32  = smem_u32(sm + SM_S);
    uint32_t wh32 = smem_u32(sm + SM_WH);
    uint32_t wl32 = smem_u32(sm + SM_WL);
    uint32_t ph32 = smem_u32(sm + SM_PHIH);
    uint32_t pl32 = smem_u32(sm + SM_PHIL);

    // ============================ HAT PHASE ============================
    float C[2][8][4];
#pragma unroll
    for (int mi = 0; mi < 2; mi++)
#pragma unroll
        for (int j = 0; j < 8; j++)
#pragma unroll
            for (int q = 0; q < 4; q++) C[mi][j][q] = 0.f;

    int hh = tid >> 2, ig = tid & 3;  // w-staging roles
    int nch = (n_pos + 31) >> 5;

    for (int kc = 0; kc < nch; kc++) {
        int i0 = kc * 32;
        __syncthreads();
        // stage seq chunk: [b=tid][32 i] bf16, pitch 80B (exact: seq is +/-1)
        {
            const float4* sp = (const float4*)(seq + tid * 512 + i0);
            uint32_t pk[16];
#pragma unroll
            for (int j = 0; j < 8; j++) {
                float4 v = sp[j];
                pk[2 * j]     = packbf(v.x, v.y);
                pk[2 * j + 1] = packbf(v.z, v.w);
            }
            uint4* d = (uint4*)(sm + SM_S + tid * 80);
            d[0] = make_uint4(pk[0], pk[1], pk[2], pk[3]);
            d[1] = make_uint4(pk[4], pk[5], pk[6], pk[7]);
            d[2] = make_uint4(pk[8], pk[9], pk[10], pk[11]);
            d[3] = make_uint4(pk[12], pk[13], pk[14], pk[15]);
        }
        // stage softmax weights: [i][h] hi/lo bf16, pitch 144B
        {
            float rmx = rmax_s[hh], riv = rinv_s[hh];
            const float4* ap = (const float4*)(Alog + (size_t)(n_pos * 64 + hh) * 512 + i0 + ig * 8);
            float4 v0 = ap[0], v1 = ap[1];
            float vv[8] = {v0.x, v0.y, v0.z, v0.w, v1.x, v1.y, v1.z, v1.w};
#pragma unroll
            for (int j = 0; j < 8; j++) {
                int i = i0 + ig * 8 + j;
                float wv = (i < n_pos) ? exp2f((vv[j] - rmx) * L2E) * riv : 0.f;
                __nv_bfloat16 hb = __float2bfloat16(wv);
                int il = ig * 8 + j;
                *(__nv_bfloat16*)(sm + SM_WH + il * 144 + hh * 2) = hb;
                *(__nv_bfloat16*)(sm + SM_WL + il * 144 + hh * 2) =
                    __float2bfloat16(wv - __bfloat162float(hb));
            }
        }
        __syncthreads();

#pragma unroll
        for (int ks = 0; ks < 2; ks++) {
            uint32_t aS[2][4];
#pragma unroll
            for (int mi = 0; mi < 2; mi++)
                ldsm_x4(aS[mi], s32 + (wid * 32 + mi * 16 + (ln & 15)) * 80 +
                                 ks * 32 + (ln >> 4) * 16);
#pragma unroll
            for (int nt = 0; nt < 4; nt++) {
                uint32_t wHf[4], wLf[4];
                uint32_t off = (ks * 16 + (ln & 15)) * 144 + (nt * 16 + (ln >> 4) * 8) * 2;
                ldsm_x4t(wHf, wh32 + off);
                ldsm_x4t(wLf, wl32 + off);
#pragma unroll
                for (int mi = 0; mi < 2; mi++) {
#pragma unroll
                    for (int t2 = 0; t2 < 2; t2++) {
                        mma_bf16(C[mi][nt * 2 + t2], aS[mi], wHf[t2 * 2], wHf[t2 * 2 + 1]);
                        mma_bf16(C[mi][nt * 2 + t2], aS[mi], wLf[t2 * 2], wLf[t2 * 2 + 1]);
                    }
                }
            }
        }
    }

    // ================= CONVERT hat C-frags -> score A-frags =================
    uint32_t aH[2][4][4], aL[2][4][4];
#pragma unroll
    for (int mi = 0; mi < 2; mi++) {
#pragma unroll
        for (int kj = 0; kj < 4; kj++) {
            const float* t0 = C[mi][2 * kj];
            const float* t1 = C[mi][2 * kj + 1];
            aH[mi][kj][0] = packbf(t0[0], t0[1]);
            aH[mi][kj][1] = packbf(t0[2], t0[3]);
            aH[mi][kj][2] = packbf(t1[0], t1[1]);
            aH[mi][kj][3] = packbf(t1[2], t1[3]);
            aL[mi][kj][0] = packresid(aH[mi][kj][0], t0[0], t0[1]);
            aL[mi][kj][1] = packresid(aH[mi][kj][1], t0[2], t0[3]);
            aL[mi][kj][2] = packresid(aH[mi][kj][2], t1[0], t1[1]);
            aL[mi][kj][3] = packresid(aH[mi][kj][3], t1[2], t1[3]);
        }
    }

    // ============================ SCORE PHASE ============================
    float num[2][2] = {{0.f, 0.f}, {0.f, 0.f}};
    float den[2][2] = {{0.f, 0.f}, {0.f, 0.f}};

    for (int c = 0; c < 4; c++) {
        __syncthreads();
#pragma unroll
        for (int it = 0; it < 8; it++) {
            int idx = it * 256 + tid;
            int r = idx >> 5, q = idx & 31;
            *(uint4*)(sm + SM_PHIH + r * 528 + q * 16) =
                *(const uint4*)(g_phiTH + r * 1024 + c * 256 + q * 8);
            *(uint4*)(sm + SM_PHIL + r * 528 + q * 16) =
                *(const uint4*)(g_phiTL + r * 1024 + c * 256 + q * 8);
        }
        __syncthreads();

        for (int pr = 0; pr < 16; pr++) {
            float cc[2][2][4];
#pragma unroll
            for (int mi = 0; mi < 2; mi++)
#pragma unroll
                for (int t2 = 0; t2 < 2; t2++)
#pragma unroll
                    for (int q = 0; q < 4; q++) cc[mi][t2][q] = 0.f;

#pragma unroll
            for (int kj = 0; kj < 4; kj++) {
                uint32_t bH[4], bL[4];
                uint32_t off = (kj * 16 + (ln & 15)) * 528 +
                               (pr * 16 + (ln >> 4) * 8) * 2;
                ldsm_x4t(bH, ph32 + off);
                ldsm_x4t(bL, pl32 + off);
#pragma unroll
                for (int mi = 0; mi < 2; mi++) {
#pragma unroll
                    for (int t2 = 0; t2 < 2; t2++) {
                        mma_bf16(cc[mi][t2], aH[mi][kj], bH[t2 * 2], bH[t2 * 2 + 1]);
                        mma_bf16(cc[mi][t2], aH[mi][kj], bL[t2 * 2], bL[t2 * 2 + 1]);
                        mma_bf16(cc[mi][t2], aL[mi][kj], bH[t2 * 2], bH[t2 * 2 + 1]);
                    }
                }
            }
            int mbase = c * 256 + pr * 16;
#pragma unroll
            for (int mi = 0; mi < 2; mi++) {
#pragma unroll
                for (int t2 = 0; t2 < 2; t2++) {
                    int mc = mbase + t2 * 8 + 2 * (ln & 3);
                    float p0 = plus_s[mc], p1 = plus_s[mc + 1];
                    float e0 = __expf(cc[mi][t2][0]);
                    float e1 = __expf(cc[mi][t2][1]);
                    float e2 = __expf(cc[mi][t2][2]);
                    float e3 = __expf(cc[mi][t2][3]);
                    den[mi][0] += e0 + e1; num[mi][0] += e0 * p0 + e1 * p1;
                    den[mi][1] += e2 + e3; num[mi][1] += e2 * p0 + e3 * p1;
                }
            }
        }
    }

    // reduce over the 4 lanes sharing each row (ln&3)
#pragma unroll
    for (int o = 1; o <= 2; o <<= 1) {
#pragma unroll
        for (int mi = 0; mi < 2; mi++)
#pragma unroll
            for (int ri = 0; ri < 2; ri++) {
                num[mi][ri] += __shfl_xor_sync(0xffffffffu, num[mi][ri], o);
                den[mi][ri] += __shfl_xor_sync(0xffffffffu, den[mi][ri], o);
            }
    }
    if ((ln & 3) == 0) {
        int r = ln >> 2;
        float bce = 0.f;
#pragma unroll
        for (int mi = 0; mi < 2; mi++) {
#pragma unroll
            for (int ri = 0; ri < 2; ri++) {
                int b = wid * 32 + mi * 16 + ri * 8 + r;
                float prob = num[mi][ri] / den[mi][ri];
                prob = fminf(fmaxf(prob, 1e-6f), 1.0f - 1e-6f);
                bool t = seq[b * 512 + n_pos] > 0.0f;
                bce += t ? -logf(prob) : -log1pf(-prob);
            }
        }
        red[wid * 8 + r] = bce;
    }
    __syncthreads();
    if (tid == 0) {
        double s = 0.0;
#pragma unroll
        for (int i = 0; i < 64; i++) s += (double)red[i];
        atomicAdd(&g_acc, s);
    }
}

__global__ void k_final(float* out) {
    out[0] = (float)(g_acc * (1.0 / (256.0 * 511.0)));
}

// ---------------------------------------------------------------------------
extern "C" void kernel_launch(void* const* d_in, const int* in_sizes, int n_in,
                              void* d_out, int out_size) {
    const float *seq = 0, *mem = 0, *Al = 0, *Bl = 0;
    for (int i = 0; i < n_in; i++) {
        switch (in_sizes[i]) {
            case 131072:   seq = (const float*)d_in[i]; break;  // (256,512)
            case 524288:   mem = (const float*)d_in[i]; break;  // (1024,512)
            case 16777216: Al  = (const float*)d_in[i]; break;  // (512,64,512)
            case 32768:    Bl  = (const float*)d_in[i]; break;  // (64,512)
        }
    }
    if (!seq) seq = (const float*)d_in[0];
    if (!mem) mem = (const float*)d_in[1];
    if (!Al)  Al  = (const float*)d_in[2];
    if (!Bl)  Bl  = (const float*)d_in[3];

    cudaFuncSetAttribute(k_fused, cudaFuncAttributeMaxDynamicSharedMemorySize, SM_TOTAL);

    k_zero<<<1, 1>>>();
    k_bn<<<64, 32>>>(Bl);
    k_phi<<<1024, 128>>>(mem);
    k_rowstats<<<4088, 256>>>(Al);
    k_fused<<<511, 256, SM_TOTAL>>>(Al, seq, mem);
    k_final<<<1, 1>>>((float*)d_out);
}

// round 5
// speedup vs baseline: 4.0354x; 1.1241x over previous
#include <cuda_runtime.h>
#include <cuda_bf16.h>
#include <math.h>
#include <stdint.h>

// Problem constants: N=512, H=64, M=1024, B=256, ETA=1
#define L2E 1.4426950408889634f

// ---------------------------------------------------------------------------
__device__ __forceinline__ uint32_t smem_u32(const void* p) {
    uint32_t a;
    asm("{ .reg .u64 t; cvta.to.shared.u64 t, %1; cvt.u32.u64 %0, t; }" : "=r"(a) : "l"(p));
    return a;
}
__device__ __forceinline__ void ldsm_x4(uint32_t r[4], uint32_t addr) {
    asm volatile("ldmatrix.sync.aligned.m8n8.x4.shared.b16 {%0,%1,%2,%3}, [%4];"
                 : "=r"(r[0]), "=r"(r[1]), "=r"(r[2]), "=r"(r[3]) : "r"(addr));
}
__device__ __forceinline__ void ldsm_x4t(uint32_t r[4], uint32_t addr) {
    asm volatile("ldmatrix.sync.aligned.m8n8.x4.trans.shared.b16 {%0,%1,%2,%3}, [%4];"
                 : "=r"(r[0]), "=r"(r[1]), "=r"(r[2]), "=r"(r[3]) : "r"(addr));
}
__device__ __forceinline__ void mma_bf16(float c[4], const uint32_t a[4],
                                         uint32_t b0, uint32_t b1) {
    asm volatile("mma.sync.aligned.m16n8k16.row.col.f32.bf16.bf16.f32 "
                 "{%0,%1,%2,%3}, {%4,%5,%6,%7}, {%8,%9}, {%0,%1,%2,%3};"
                 : "+f"(c[0]), "+f"(c[1]), "+f"(c[2]), "+f"(c[3])
                 : "r"(a[0]), "r"(a[1]), "r"(a[2]), "r"(a[3]), "r"(b0), "r"(b1));
}
__device__ __forceinline__ uint32_t packbf(float lo, float hi) {
    uint32_t d;
    asm("cvt.rn.bf16x2.f32 %0, %1, %2;" : "=r"(d) : "f"(hi), "f"(lo));
    return d;
}
__device__ __forceinline__ uint32_t packresid(uint32_t p, float f0, float f1) {
    float r0 = f0 - __uint_as_float(p << 16);
    float r1 = f1 - __uint_as_float(p & 0xffff0000u);
    return packbf(r0, r1);
}

// ---------------------------------------------------------------------------
// Scratch
__device__ float  g_Bn[64 * 512];
__device__ __align__(16) __nv_bfloat16 g_phiTH[64 * 1024];  // hi(phi) [h][m]
__device__ __align__(16) __nv_bfloat16 g_phiTL[64 * 1024];  // lo(phi)
__device__ __align__(16) uint32_t g_seqbf[256 * 256];       // seq bf16 [b][512]
__device__ double g_acc;

__global__ void k_zero() { g_acc = 0.0; }

// ---------------------------------------------------------------------------
__global__ void k_bn(const float* __restrict__ Blog) {
    int h = blockIdx.x, l = threadIdx.x;
    const float* row = Blog + h * 512;
    float x[16];
    float mx = -3.402823466e38f;
#pragma unroll
    for (int k = 0; k < 16; k++) { x[k] = row[l + k * 32]; mx = fmaxf(mx, x[k]); }
#pragma unroll
    for (int o = 16; o; o >>= 1) mx = fmaxf(mx, __shfl_xor_sync(0xffffffffu, mx, o));
    float s = 0.f;
#pragma unroll
    for (int k = 0; k < 16; k++) { x[k] = exp2f((x[k] - mx) * L2E); s += x[k]; }
#pragma unroll
    for (int o = 16; o; o >>= 1) s += __shfl_xor_sync(0xffffffffu, s, o);
    float inv = 1.0f / s;
#pragma unroll
    for (int k = 0; k < 16; k++) g_Bn[h * 512 + l + k * 32] = x[k] * inv;
}

__global__ void k_phi(const float* __restrict__ mem) {
    __shared__ float row[512];
    int m = blockIdx.x, tid = threadIdx.x;
    for (int i = tid; i < 512; i += 128) row[i] = mem[m * 512 + i];
    __syncthreads();
    int w = tid >> 5, l = tid & 31;
#pragma unroll 4
    for (int hh = 0; hh < 16; hh++) {
        int h = w * 16 + hh;
        float a = 0.f;
#pragma unroll
        for (int k = 0; k < 16; k++) { int i = l + k * 32; a += g_Bn[h * 512 + i] * row[i]; }
#pragma unroll
        for (int o = 16; o; o >>= 1) a += __shfl_xor_sync(0xffffffffu, a, o);
        if (l == 0) {
            __nv_bfloat16 hi = __float2bfloat16(a);
            g_phiTH[h * 1024 + m] = hi;
            g_phiTL[h * 1024 + m] = __float2bfloat16(a - __bfloat162float(hi));
        }
    }
}

__global__ void k_seqbf(const float* __restrict__ seq) {
    int idx = blockIdx.x * 256 + threadIdx.x;  // 0..32767, 4 floats each
    float4 v = ((const float4*)seq)[idx];
    uint2 o;
    o.x = packbf(v.x, v.y);
    o.y = packbf(v.z, v.w);
    ((uint2*)g_seqbf)[idx] = o;
}

// ---------------------------------------------------------------------------
// FUSED kernel: hat GEMM (unnormalized-exp weights, tensor) -> Z normalize ->
// in-register A-frag conversion -> score GEMM -> softmax retrieval -> BCE.
// One CTA per n (511), 256 threads; warp w owns b-rows [w*32, w*32+32).
// Both phases register-pipelined with double-buffered smem.
#define SM_RED   0
#define SM_INVZ  256
#define SM_PLUS  512
#define SM_DYN   4608
// hat buffers (stride 29952): WH [32i][64h] pitch 144 (4608B), WL +4608, S [256b][32i] pitch 80 (+9216)
#define HB_WH 0
#define HB_WL 4608
#define HB_S  9216
#define HB_STRIDE 29952
// score buffers (stride 34816): PHIH [64h][128m] pitch 272 (17408B), PHIL +17408
#define PB_H 0
#define PB_L 17408
#define PB_STRIDE 34816
#define SM_TOTAL (SM_DYN + 2 * PB_STRIDE)

struct HatSt { float4 a0, a1; uint4 s[4]; };

__device__ __forceinline__ void hat_ldg(HatSt& st, const float* __restrict__ Alog,
                                        int n_pos, int hh, int ig, int i0, int tid) {
    const float4* ap = (const float4*)(Alog + (size_t)(n_pos * 64 + hh) * 512 + i0 + ig * 8);
    st.a0 = ap[0]; st.a1 = ap[1];
    const uint4* sp = (const uint4*)g_seqbf + tid * 64 + (i0 >> 3);
#pragma unroll
    for (int u = 0; u < 4; u++) st.s[u] = sp[u];
}

__device__ __forceinline__ void hat_sts(const HatSt& st, char* sm, int buf,
                                        int n_pos, int hh, int ig, int i0, int tid,
                                        float& zpart) {
    char* base = sm + SM_DYN + buf * HB_STRIDE;
    uint4* d = (uint4*)(base + HB_S + tid * 80);
#pragma unroll
    for (int u = 0; u < 4; u++) d[u] = st.s[u];
    float vv[8] = { st.a0.x, st.a0.y, st.a0.z, st.a0.w,
                    st.a1.x, st.a1.y, st.a1.z, st.a1.w };
#pragma unroll
    for (int j = 0; j < 8; j++) {
        int i = i0 + ig * 8 + j;
        float w = (i < n_pos) ? __expf(vv[j]) : 0.f;
        zpart += w;
        __nv_bfloat16 hb = __float2bfloat16(w);
        int il = ig * 8 + j;
        *(__nv_bfloat16*)(base + HB_WH + il * 144 + hh * 2) = hb;
        *(__nv_bfloat16*)(base + HB_WL + il * 144 + hh * 2) =
            __float2bfloat16(w - __bfloat162float(hb));
    }
}

__device__ __forceinline__ void score_ldg(uint4 r8[8], int c, int tid) {
#pragma unroll
    for (int it = 0; it < 4; it++) {
        int idx = it * 256 + tid;
        int r = idx >> 4, q = idx & 15;
        r8[it]     = *(const uint4*)(g_phiTH + r * 1024 + c * 128 + q * 8);
        r8[it + 4] = *(const uint4*)(g_phiTL + r * 1024 + c * 128 + q * 8);
    }
}
__device__ __forceinline__ void score_sts(const uint4 r8[8], char* sm, int buf, int tid) {
    char* base = sm + SM_DYN + buf * PB_STRIDE;
#pragma unroll
    for (int it = 0; it < 4; it++) {
        int idx = it * 256 + tid;
        int r = idx >> 4, q = idx & 15;
        *(uint4*)(base + PB_H + r * 272 + q * 16) = r8[it];
        *(uint4*)(base + PB_L + r * 272 + q * 16) = r8[it + 4];
    }
}

__global__ void __launch_bounds__(256, 2) k_fused(const float* __restrict__ Alog,
                                                  const float* __restrict__ seq,
                                                  const float* __restrict__ mem) {
    extern __shared__ char sm[];
    int tid = threadIdx.x, wid = tid >> 5, ln = tid & 31;
    int n_idx = 510 - blockIdx.x, n_pos = n_idx + 1;

    float* red    = (float*)(sm + SM_RED);
    float* invZ_s = (float*)(sm + SM_INVZ);
    float* plus_s = (float*)(sm + SM_PLUS);

#pragma unroll
    for (int q = 0; q < 4; q++) {
        int m = q * 256 + tid;
        plus_s[m] = (mem[(size_t)m * 512 + n_pos] > 0.0f) ? 1.0f : 0.0f;
    }

    uint32_t dynb = smem_u32(sm + SM_DYN);

    // ============================ HAT PHASE ============================
    float C[2][8][4];
#pragma unroll
    for (int mi = 0; mi < 2; mi++)
#pragma unroll
        for (int j = 0; j < 8; j++)
#pragma unroll
            for (int q = 0; q < 4; q++) C[mi][j][q] = 0.f;

    int hh = tid >> 2, ig = tid & 3;
    float zpart = 0.f;
    int nch = (n_pos + 31) >> 5;

    HatSt st;
    hat_ldg(st, Alog, n_pos, hh, ig, 0, tid);
    hat_sts(st, sm, 0, n_pos, hh, ig, 0, tid, zpart);
    __syncthreads();
    if (nch > 1) hat_ldg(st, Alog, n_pos, hh, ig, 32, tid);

    for (int kc = 0; kc < nch; kc++) {
        uint32_t Bb = dynb + (kc & 1) * HB_STRIDE;
#pragma unroll
        for (int ks = 0; ks < 2; ks++) {
            uint32_t aS[2][4];
#pragma unroll
            for (int mi = 0; mi < 2; mi++)
                ldsm_x4(aS[mi], Bb + HB_S + (wid * 32 + mi * 16 + (ln & 15)) * 80 +
                                 ks * 32 + (ln >> 4) * 16);
#pragma unroll
            for (int nt = 0; nt < 4; nt++) {
                uint32_t wHf[4], wLf[4];
                uint32_t off = (ks * 16 + (ln & 15)) * 144 + (nt * 16 + (ln >> 4) * 8) * 2;
                ldsm_x4t(wHf, Bb + HB_WH + off);
                ldsm_x4t(wLf, Bb + HB_WL + off);
#pragma unroll
                for (int mi = 0; mi < 2; mi++) {
#pragma unroll
                    for (int t2 = 0; t2 < 2; t2++) {
                        mma_bf16(C[mi][nt * 2 + t2], aS[mi], wHf[t2 * 2], wHf[t2 * 2 + 1]);
                        mma_bf16(C[mi][nt * 2 + t2], aS[mi], wLf[t2 * 2], wLf[t2 * 2 + 1]);
                    }
                }
            }
        }
        if (kc + 1 < nch)
            hat_sts(st, sm, (kc + 1) & 1, n_pos, hh, ig, (kc + 1) * 32, tid, zpart);
        __syncthreads();
        if (kc + 2 < nch) hat_ldg(st, Alog, n_pos, hh, ig, (kc + 2) * 32, tid);
    }

    // Z reduce (4 lanes per h, consecutive) and normalize C
    zpart += __shfl_xor_sync(0xffffffffu, zpart, 1);
    zpart += __shfl_xor_sync(0xffffffffu, zpart, 2);
    if ((tid & 3) == 0) invZ_s[hh] = 1.0f / zpart;
    __syncthreads();

#pragma unroll
    for (int j = 0; j < 8; j++) {
        int h0 = j * 8 + 2 * (ln & 3);
        float iz0 = invZ_s[h0], iz1 = invZ_s[h0 + 1];
#pragma unroll
        for (int mi = 0; mi < 2; mi++) {
            C[mi][j][0] *= iz0; C[mi][j][1] *= iz1;
            C[mi][j][2] *= iz0; C[mi][j][3] *= iz1;
        }
    }

    // ================= CONVERT hat C-frags -> score A-frags =================
    uint32_t aH[2][4][4], aL[2][4][4];
#pragma unroll
    for (int mi = 0; mi < 2; mi++) {
#pragma unroll
        for (int kj = 0; kj < 4; kj++) {
            const float* t0 = C[mi][2 * kj];
            const float* t1 = C[mi][2 * kj + 1];
            aH[mi][kj][0] = packbf(t0[0], t0[1]);
            aH[mi][kj][1] = packbf(t0[2], t0[3]);
            aH[mi][kj][2] = packbf(t1[0], t1[1]);
            aH[mi][kj][3] = packbf(t1[2], t1[3]);
            aL[mi][kj][0] = packresid(aH[mi][kj][0], t0[0], t0[1]);
            aL[mi][kj][1] = packresid(aH[mi][kj][1], t0[2], t0[3]);
            aL[mi][kj][2] = packresid(aH[mi][kj][2], t1[0], t1[1]);
            aL[mi][kj][3] = packresid(aH[mi][kj][3], t1[2], t1[3]);
        }
    }

    // ============================ SCORE PHASE ============================
    float num[2][2] = {{0.f, 0.f}, {0.f, 0.f}};
    float den[2][2] = {{0.f, 0.f}, {0.f, 0.f}};

    uint4 r8[8];
    score_ldg(r8, 0, tid);
    score_sts(r8, sm, 0, tid);
    __syncthreads();
    score_ldg(r8, 1, tid);

    for (int c = 0; c < 8; c++) {
        uint32_t Pb = dynb + (c & 1) * PB_STRIDE;
#pragma unroll
        for (int pr = 0; pr < 8; pr++) {
            float cc[2][2][4];
#pragma unroll
            for (int mi = 0; mi < 2; mi++)
#pragma unroll
                for (int t2 = 0; t2 < 2; t2++)
#pragma unroll
                    for (int q = 0; q < 4; q++) cc[mi][t2][q] = 0.f;

#pragma unroll
            for (int kj = 0; kj < 4; kj++) {
                uint32_t bH[4], bL[4];
                uint32_t off = (kj * 16 + (ln & 15)) * 272 + (pr * 16 + (ln >> 4) * 8) * 2;
                ldsm_x4t(bH, Pb + PB_H + off);
                ldsm_x4t(bL, Pb + PB_L + off);
#pragma unroll
                for (int mi = 0; mi < 2; mi++) {
#pragma unroll
                    for (int t2 = 0; t2 < 2; t2++) {
                        mma_bf16(cc[mi][t2], aH[mi][kj], bH[t2 * 2], bH[t2 * 2 + 1]);
                        mma_bf16(cc[mi][t2], aH[mi][kj], bL[t2 * 2], bL[t2 * 2 + 1]);
                        mma_bf16(cc[mi][t2], aL[mi][kj], bH[t2 * 2], bH[t2 * 2 + 1]);
                    }
                }
            }
            int mbase = c * 128 + pr * 16;
#pragma unroll
            for (int mi = 0; mi < 2; mi++) {
#pragma unroll
                for (int t2 = 0; t2 < 2; t2++) {
                    int mc = mbase + t2 * 8 + 2 * (ln & 3);
                    float p0 = plus_s[mc], p1 = plus_s[mc + 1];
                    float e0 = __expf(cc[mi][t2][0]);
                    float e1 = __expf(cc[mi][t2][1]);
                    float e2 = __expf(cc[mi][t2][2]);
                    float e3 = __expf(cc[mi][t2][3]);
                    den[mi][0] += e0 + e1; num[mi][0] += e0 * p0 + e1 * p1;
                    den[mi][1] += e2 + e3; num[mi][1] += e2 * p0 + e3 * p1;
                }
            }
        }
        if (c + 1 < 8) score_sts(r8, sm, (c + 1) & 1, tid);
        __syncthreads();
        if (c + 2 < 8) score_ldg(r8, c + 2, tid);
    }

    // reduce over the 4 lanes sharing each row
#pragma unroll
    for (int o = 1; o <= 2; o <<= 1) {
#pragma unroll
        for (int mi = 0; mi < 2; mi++)
#pragma unroll
            for (int ri = 0; ri < 2; ri++) {
                num[mi][ri] += __shfl_xor_sync(0xffffffffu, num[mi][ri], o);
                den[mi][ri] += __shfl_xor_sync(0xffffffffu, den[mi][ri], o);
            }
    }
    if ((ln & 3) == 0) {
        int r = ln >> 2;
        float bce = 0.f;
#pragma unroll
        for (int mi = 0; mi < 2; mi++) {
#pragma unroll
            for (int ri = 0; ri < 2; ri++) {
                int b = wid * 32 + mi * 16 + ri * 8 + r;
                float prob = num[mi][ri] / den[mi][ri];
                prob = fminf(fmaxf(prob, 1e-6f), 1.0f - 1e-6f);
                bool t = seq[b * 512 + n_pos] > 0.0f;
                bce += t ? -logf(prob) : -log1pf(-prob);
            }
        }
        red[wid * 8 + r] = bce;
    }
    __syncthreads();
    if (tid == 0) {
        double s = 0.0;
#pragma unroll
        for (int i = 0; i < 64; i++) s += (double)red[i];
        atomicAdd(&g_acc, s);
    }
}

__global__ void k_final(float* out) {
    out[0] = (float)(g_acc * (1.0 / (256.0 * 511.0)));
}

// ---------------------------------------------------------------------------
extern "C" void kernel_launch(void* const* d_in, const int* in_sizes, int n_in,
                              void* d_out, int out_size) {
    const float *seq = 0, *mem = 0, *Al = 0, *Bl = 0;
    for (int i = 0; i < n_in; i++) {
        switch (in_sizes[i]) {
            case 131072:   seq = (const float*)d_in[i]; break;  // (256,512)
            case 524288:   mem = (const float*)d_in[i]; break;  // (1024,512)
            case 16777216: Al  = (const float*)d_in[i]; break;  // (512,64,512)
            case 32768:    Bl  = (const float*)d_in[i]; break;  // (64,512)
        }
    }
    if (!seq) seq = (const float*)d_in[0];
    if (!mem) mem = (const float*)d_in[1];
    if (!Al)  Al  = (const float*)d_in[2];
    if (!Bl)  Bl  = (const float*)d_in[3];

    cudaFuncSetAttribute(k_fused, cudaFuncAttributeMaxDynamicSharedMemorySize, SM_TOTAL);

    k_zero<<<1, 1>>>();
    k_bn<<<64, 32>>>(Bl);
    k_phi<<<1024, 128>>>(mem);
    k_seqbf<<<128, 256>>>(seq);
    k_fused<<<511, 256, SM_TOTAL>>>(Al, seq, mem);
    k_final<<<1, 1>>>((float*)d_out);
}

// round 7
// speedup vs baseline: 6.3306x; 1.5687x over previous
#include <cuda_runtime.h>
#include <cuda_fp16.h>
#include <math.h>
#include <stdint.h>

// Problem constants: N=512, H=64, M=1024, B=256, ETA=1
#define L2E 1.4426950408889634f

// ---------------------------------------------------------------------------
__device__ __forceinline__ uint32_t smem_u32(const void* p) {
    uint32_t a;
    asm("{ .reg .u64 t; cvta.to.shared.u64 t, %1; cvt.u32.u64 %0, t; }" : "=r"(a) : "l"(p));
    return a;
}
__device__ __forceinline__ void ldsm_x4(uint32_t r[4], uint32_t addr) {
    asm volatile("ldmatrix.sync.aligned.m8n8.x4.shared.b16 {%0,%1,%2,%3}, [%4];"
                 : "=r"(r[0]), "=r"(r[1]), "=r"(r[2]), "=r"(r[3]) : "r"(addr));
}
__device__ __forceinline__ void ldsm_x4t(uint32_t r[4], uint32_t addr) {
    asm volatile("ldmatrix.sync.aligned.m8n8.x4.trans.shared.b16 {%0,%1,%2,%3}, [%4];"
                 : "=r"(r[0]), "=r"(r[1]), "=r"(r[2]), "=r"(r[3]) : "r"(addr));
}
__device__ __forceinline__ void mma_f16(float c[4], const uint32_t a[4],
                                        uint32_t b0, uint32_t b1) {
    asm volatile("mma.sync.aligned.m16n8k16.row.col.f32.f16.f16.f32 "
                 "{%0,%1,%2,%3}, {%4,%5,%6,%7}, {%8,%9}, {%0,%1,%2,%3};"
                 : "+f"(c[0]), "+f"(c[1]), "+f"(c[2]), "+f"(c[3])
                 : "r"(a[0]), "r"(a[1]), "r"(a[2]), "r"(a[3]), "r"(b0), "r"(b1));
}
// pack two f32 -> f16x2 (first arg in low half)
__device__ __forceinline__ uint32_t packhf(float lo, float hi) {
    uint32_t d;
    asm("cvt.rn.f16x2.f32 %0, %1, %2;" : "=r"(d) : "f"(hi), "f"(lo));
    return d;
}

// ---------------------------------------------------------------------------
// Scratch
__device__ float  g_Bn[64 * 512];
__device__ __align__(16) __half g_phiF[64 * 1024];    // phi fp16 [h][m]
__device__ __align__(16) uint32_t g_seqhf[256 * 256]; // seq fp16 [b][512]
__device__ double g_acc;

__global__ void k_zero() { g_acc = 0.0; }

// ---------------------------------------------------------------------------
__global__ void k_bn(const float* __restrict__ Blog) {
    int h = blockIdx.x, l = threadIdx.x;
    const float* row = Blog + h * 512;
    float x[16];
    float mx = -3.402823466e38f;
#pragma unroll
    for (int k = 0; k < 16; k++) { x[k] = row[l + k * 32]; mx = fmaxf(mx, x[k]); }
#pragma unroll
    for (int o = 16; o; o >>= 1) mx = fmaxf(mx, __shfl_xor_sync(0xffffffffu, mx, o));
    float s = 0.f;
#pragma unroll
    for (int k = 0; k < 16; k++) { x[k] = exp2f((x[k] - mx) * L2E); s += x[k]; }
#pragma unroll
    for (int o = 16; o; o >>= 1) s += __shfl_xor_sync(0xffffffffu, s, o);
    float inv = 1.0f / s;
#pragma unroll
    for (int k = 0; k < 16; k++) g_Bn[h * 512 + l + k * 32] = x[k] * inv;
}

__global__ void k_phi(const float* __restrict__ mem) {
    __shared__ float row[512];
    int m = blockIdx.x, tid = threadIdx.x;
    for (int i = tid; i < 512; i += 128) row[i] = mem[m * 512 + i];
    __syncthreads();
    int w = tid >> 5, l = tid & 31;
#pragma unroll 4
    for (int hh = 0; hh < 16; hh++) {
        int h = w * 16 + hh;
        float a = 0.f;
#pragma unroll
        for (int k = 0; k < 16; k++) { int i = l + k * 32; a += g_Bn[h * 512 + i] * row[i]; }
#pragma unroll
        for (int o = 16; o; o >>= 1) a += __shfl_xor_sync(0xffffffffu, a, o);
        if (l == 0) g_phiF[h * 1024 + m] = __float2half(a);
    }
}

__global__ void k_seqhf(const float* __restrict__ seq) {
    int idx = blockIdx.x * 256 + threadIdx.x;  // 0..32767, 4 floats each
    float4 v = ((const float4*)seq)[idx];
    uint2 o;
    o.x = packhf(v.x, v.y);
    o.y = packhf(v.z, v.w);
    ((uint2*)g_seqhf)[idx] = o;
}

// ---------------------------------------------------------------------------
// FUSED kernel, fp16 single-term: hat GEMM (unnormalized-exp weights) ->
// Z normalize -> register A-frag conversion -> score GEMM -> retrieval -> BCE.
// One CTA per n (511), 256 threads; warp w owns b-rows [w*32, w*32+32).
#define SM_RED   0
#define SM_INVZ  256
#define SM_PLUS  512
#define SM_DYN   4608
// hat buffers: W [32i][64h] fp16 pitch 144 (4608B); S [256b][32i] fp16 pitch 80 (20480B)
#define HB_W 0
#define HB_S 4608
#define HB_STRIDE 25088
// score buffers: PH [64h][128m] fp16 pitch 272 (17408B)
#define PB_STRIDE 17408
#define SM_TOTAL (SM_DYN + 2 * HB_STRIDE)

struct HatSt { float4 a0, a1; uint4 s[4]; };

__device__ __forceinline__ void hat_ldg(HatSt& st, const float* __restrict__ Alog,
                                        int n_pos, int hh, int ig, int i0, int tid) {
    const float4* ap = (const float4*)(Alog + (size_t)(n_pos * 64 + hh) * 512 + i0 + ig * 8);
    st.a0 = ap[0]; st.a1 = ap[1];
    // g_seqhf row = 512 fp16 = 64 uint4; chunk of 32 i = 4 uint4
    const uint4* sp = (const uint4*)g_seqhf + tid * 64 + (i0 >> 3);
#pragma unroll
    for (int u = 0; u < 4; u++) st.s[u] = sp[u];
}

__device__ __forceinline__ void hat_sts(const HatSt& st, char* sm, int buf,
                                        int n_pos, int hh, int ig, int i0, int tid,
                                        float& zpart) {
    char* base = sm + SM_DYN + buf * HB_STRIDE;
    uint4* d = (uint4*)(base + HB_S + tid * 80);
#pragma unroll
    for (int u = 0; u < 4; u++) d[u] = st.s[u];
    float vv[8] = { st.a0.x, st.a0.y, st.a0.z, st.a0.w,
                    st.a1.x, st.a1.y, st.a1.z, st.a1.w };
#pragma unroll
    for (int j = 0; j < 8; j++) {
        int i = i0 + ig * 8 + j;
        float w = (i < n_pos) ? __expf(vv[j]) : 0.f;
        zpart += w;
        *(__half*)(base + HB_W + (ig * 8 + j) * 144 + hh * 2) = __float2half(w);
    }
}

__device__ __forceinline__ void score_ldg(uint4 r4[4], int c, int tid) {
#pragma unroll
    for (int it = 0; it < 4; it++) {
        int idx = it * 256 + tid;
        int r = idx >> 4, q = idx & 15;
        r4[it] = *(const uint4*)(g_phiF + r * 1024 + c * 128 + q * 8);
    }
}
__device__ __forceinline__ void score_sts(const uint4 r4[4], char* sm, int buf, int tid) {
    char* base = sm + SM_DYN + buf * PB_STRIDE;
#pragma unroll
    for (int it = 0; it < 4; it++) {
        int idx = it * 256 + tid;
        int r = idx >> 4, q = idx & 15;
        *(uint4*)(base + r * 272 + q * 16) = r4[it];
    }
}

__global__ void __launch_bounds__(256, 2) k_fused(const float* __restrict__ Alog,
                                                  const float* __restrict__ seq,
                                                  const float* __restrict__ mem) {
    extern __shared__ char sm[];
    int tid = threadIdx.x, wid = tid >> 5, ln = tid & 31;
    int n_idx = 510 - blockIdx.x, n_pos = n_idx + 1;

    float* red    = (float*)(sm + SM_RED);
    float* invZ_s = (float*)(sm + SM_INVZ);
    float* plus_s = (float*)(sm + SM_PLUS);

#pragma unroll
    for (int q = 0; q < 4; q++) {
        int m = q * 256 + tid;
        plus_s[m] = (mem[(size_t)m * 512 + n_pos] > 0.0f) ? 1.0f : 0.0f;
    }

    uint32_t dynb = smem_u32(sm + SM_DYN);

    // ============================ HAT PHASE ============================
    float C[2][8][4];
#pragma unroll
    for (int mi = 0; mi < 2; mi++)
#pragma unroll
        for (int j = 0; j < 8; j++)
#pragma unroll
            for (int q = 0; q < 4; q++) C[mi][j][q] = 0.f;

    int hh = tid >> 2, ig = tid & 3;
    float zpart = 0.f;
    int nch = (n_pos + 31) >> 5;

    HatSt st;
    hat_ldg(st, Alog, n_pos, hh, ig, 0, tid);
    hat_sts(st, sm, 0, n_pos, hh, ig, 0, tid, zpart);
    __syncthreads();
    if (nch > 1) hat_ldg(st, Alog, n_pos, hh, ig, 32, tid);

    for (int kc = 0; kc < nch; kc++) {
        uint32_t Bb = dynb + (kc & 1) * HB_STRIDE;
#pragma unroll
        for (int ks = 0; ks < 2; ks++) {
            uint32_t aS[2][4];
#pragma unroll
            for (int mi = 0; mi < 2; mi++)
                ldsm_x4(aS[mi], Bb + HB_S + (wid * 32 + mi * 16 + (ln & 15)) * 80 +
                                 ks * 32 + (ln >> 4) * 16);
#pragma unroll
            for (int nt = 0; nt < 4; nt++) {
                uint32_t wF[4];
                uint32_t off = (ks * 16 + (ln & 15)) * 144 + (nt * 16 + (ln >> 4) * 8) * 2;
                ldsm_x4t(wF, Bb + HB_W + off);
#pragma unroll
                for (int mi = 0; mi < 2; mi++) {
                    mma_f16(C[mi][nt * 2 + 0], aS[mi], wF[0], wF[1]);
                    mma_f16(C[mi][nt * 2 + 1], aS[mi], wF[2], wF[3]);
                }
            }
        }
        if (kc + 1 < nch)
            hat_sts(st, sm, (kc + 1) & 1, n_pos, hh, ig, (kc + 1) * 32, tid, zpart);
        __syncthreads();
        if (kc + 2 < nch) hat_ldg(st, Alog, n_pos, hh, ig, (kc + 2) * 32, tid);
    }

    // Z reduce (4 lanes per h) and normalize C
    zpart += __shfl_xor_sync(0xffffffffu, zpart, 1);
    zpart += __shfl_xor_sync(0xffffffffu, zpart, 2);
    if ((tid & 3) == 0) invZ_s[hh] = 1.0f / zpart;
    __syncthreads();

#pragma unroll
    for (int j = 0; j < 8; j++) {
        int h0 = j * 8 + 2 * (ln & 3);
        float iz0 = invZ_s[h0], iz1 = invZ_s[h0 + 1];
#pragma unroll
        for (int mi = 0; mi < 2; mi++) {
            C[mi][j][0] *= iz0; C[mi][j][1] *= iz1;
            C[mi][j][2] *= iz0; C[mi][j][3] *= iz1;
        }
    }

    // ================= CONVERT hat C-frags -> score A-frags (fp16) =========
    uint32_t aF[2][4][4];
#pragma unroll
    for (int mi = 0; mi < 2; mi++) {
#pragma unroll
        for (int kj = 0; kj < 4; kj++) {
            const float* t0 = C[mi][2 * kj];
            const float* t1 = C[mi][2 * kj + 1];
            aF[mi][kj][0] = packhf(t0[0], t0[1]);
            aF[mi][kj][1] = packhf(t0[2], t0[3]);
            aF[mi][kj][2] = packhf(t1[0], t1[1]);
            aF[mi][kj][3] = packhf(t1[2], t1[3]);
        }
    }

    // ============================ SCORE PHASE ============================
    float num[2][2] = {{0.f, 0.f}, {0.f, 0.f}};
    float den[2][2] = {{0.f, 0.f}, {0.f, 0.f}};

    uint4 r4[4];
    score_ldg(r4, 0, tid);
    score_sts(r4, sm, 0, tid);
    __syncthreads();
    score_ldg(r4, 1, tid);

    for (int c = 0; c < 8; c++) {
        uint32_t Pb = dynb + (c & 1) * PB_STRIDE;
#pragma unroll
        for (int pr = 0; pr < 8; pr++) {
            float cc[2][2][4];
#pragma unroll
            for (int mi = 0; mi < 2; mi++)
#pragma unroll
                for (int t2 = 0; t2 < 2; t2++)
#pragma unroll
                    for (int q = 0; q < 4; q++) cc[mi][t2][q] = 0.f;

#pragma unroll
            for (int kj = 0; kj < 4; kj++) {
                uint32_t bF[4];
                uint32_t off = (kj * 16 + (ln & 15)) * 272 + (pr * 16 + (ln >> 4) * 8) * 2;
                ldsm_x4t(bF, Pb + off);
#pragma unroll
                for (int mi = 0; mi < 2; mi++) {
                    mma_f16(cc[mi][0], aF[mi][kj], bF[0], bF[1]);
                    mma_f16(cc[mi][1], aF[mi][kj], bF[2], bF[3]);
                }
            }
            int mbase = c * 128 + pr * 16;
#pragma unroll
            for (int mi = 0; mi < 2; mi++) {
#pragma unroll
                for (int t2 = 0; t2 < 2; t2++) {
                    int mc = mbase + t2 * 8 + 2 * (ln & 3);
                    float p0 = plus_s[mc], p1 = plus_s[mc + 1];
                    float e0 = __expf(cc[mi][t2][0]);
                    float e1 = __expf(cc[mi][t2][1]);
                    float e2 = __expf(cc[mi][t2][2]);
                    float e3 = __expf(cc[mi][t2][3]);
                    den[mi][0] += e0 + e1; num[mi][0] += e0 * p0 + e1 * p1;
                    den[mi][1] += e2 + e3; num[mi][1] += e2 * p0 + e3 * p1;
                }
            }
        }
        if (c + 1 < 8) score_sts(r4, sm, (c + 1) & 1, tid);
        __syncthreads();
        if (c + 2 < 8) score_ldg(r4, c + 2, tid);
    }

    // reduce over the 4 lanes sharing each row
#pragma unroll
    for (int o = 1; o <= 2; o <<= 1) {
#pragma unroll
        for (int mi = 0; mi < 2; mi++)
#pragma unroll
            for (int ri = 0; ri < 2; ri++) {
                num[mi][ri] += __shfl_xor_sync(0xffffffffu, num[mi][ri], o);
                den[mi][ri] += __shfl_xor_sync(0xffffffffu, den[mi][ri], o);
            }
    }
    if ((ln & 3) == 0) {
        int r = ln >> 2;
        float bce = 0.f;
#pragma unroll
        for (int mi = 0; mi < 2; mi++) {
#pragma unroll
            for (int ri = 0; ri < 2; ri++) {
                int b = wid * 32 + mi * 16 + ri * 8 + r;
                float prob = num[mi][ri] / den[mi][ri];
                prob = fminf(fmaxf(prob, 1e-6f), 1.0f - 1e-6f);
                bool t = seq[b * 512 + n_pos] > 0.0f;
                bce += t ? -logf(prob) : -log1pf(-prob);
            }
        }
        red[wid * 8 + r] = bce;
    }
    __syncthreads();
    if (tid == 0) {
        double s = 0.0;
#pragma unroll
        for (int i = 0; i < 64; i++) s += (double)red[i];
        atomicAdd(&g_acc, s);
    }
}

__global__ void k_final(float* out) {
    out[0] = (float)(g_acc * (1.0 / (256.0 * 511.0)));
}

// ---------------------------------------------------------------------------
extern "C" void kernel_launch(void* const* d_in, const int* in_sizes, int n_in,
                              void* d_out, int out_size) {
    const float *seq = 0, *mem = 0, *Al = 0, *Bl = 0;
    for (int i = 0; i < n_in; i++) {
        switch (in_sizes[i]) {
            case 131072:   seq = (const float*)d_in[i]; break;  // (256,512)
            case 524288:   mem = (const float*)d_in[i]; break;  // (1024,512)
            case 16777216: Al  = (const float*)d_in[i]; break;  // (512,64,512)
            case 32768:    Bl  = (const float*)d_in[i]; break;  // (64,512)
        }
    }
    if (!seq) seq = (const float*)d_in[0];
    if (!mem) mem = (const float*)d_in[1];
    if (!Al)  Al  = (const float*)d_in[2];
    if (!Bl)  Bl  = (const float*)d_in[3];

    cudaFuncSetAttribute(k_fused, cudaFuncAttributeMaxDynamicSharedMemorySize, SM_TOTAL);

    k_zero<<<1, 1>>>();
    k_bn<<<64, 32>>>(Bl);
    k_phi<<<1024, 128>>>(mem);
    k_seqhf<<<128, 256>>>(seq);
    k_fused<<<511, 256, SM_TOTAL>>>(Al, seq, mem);
    k_final<<<1, 1>>>((float*)d_out);
}

// round 8
// speedup vs baseline: 7.5412x; 1.1912x over previous
#include <cuda_runtime.h>
#include <cuda_fp16.h>
#include <math.h>
#include <stdint.h>

// Problem constants: N=512, H=64, M=1024, B=256, ETA=1
#define L2E 1.4426950408889634f
#define L2E2 0x3DC53DC5u  // fp16x2(log2 e)

// ---------------------------------------------------------------------------
__device__ __forceinline__ uint32_t smem_u32(const void* p) {
    uint32_t a;
    asm("{ .reg .u64 t; cvta.to.shared.u64 t, %1; cvt.u32.u64 %0, t; }" : "=r"(a) : "l"(p));
    return a;
}
__device__ __forceinline__ void ldsm_x4(uint32_t r[4], uint32_t addr) {
    asm volatile("ldmatrix.sync.aligned.m8n8.x4.shared.b16 {%0,%1,%2,%3}, [%4];"
                 : "=r"(r[0]), "=r"(r[1]), "=r"(r[2]), "=r"(r[3]) : "r"(addr));
}
__device__ __forceinline__ void ldsm_x4t(uint32_t r[4], uint32_t addr) {
    asm volatile("ldmatrix.sync.aligned.m8n8.x4.trans.shared.b16 {%0,%1,%2,%3}, [%4];"
                 : "=r"(r[0]), "=r"(r[1]), "=r"(r[2]), "=r"(r[3]) : "r"(addr));
}
// f32-accumulator MMA (hat GEMM)
__device__ __forceinline__ void mma_f16(float c[4], const uint32_t a[4],
                                        uint32_t b0, uint32_t b1) {
    asm volatile("mma.sync.aligned.m16n8k16.row.col.f32.f16.f16.f32 "
                 "{%0,%1,%2,%3}, {%4,%5,%6,%7}, {%8,%9}, {%0,%1,%2,%3};"
                 : "+f"(c[0]), "+f"(c[1]), "+f"(c[2]), "+f"(c[3])
                 : "r"(a[0]), "r"(a[1]), "r"(a[2]), "r"(a[3]), "r"(b0), "r"(b1));
}
// f16-accumulator MMA (score GEMM)
__device__ __forceinline__ void mma_f16acc(uint32_t c[2], const uint32_t a[4],
                                           uint32_t b0, uint32_t b1) {
    asm volatile("mma.sync.aligned.m16n8k16.row.col.f16.f16.f16.f16 "
                 "{%0,%1}, {%2,%3,%4,%5}, {%6,%7}, {%0,%1};"
                 : "+r"(c[0]), "+r"(c[1])
                 : "r"(a[0]), "r"(a[1]), "r"(a[2]), "r"(a[3]), "r"(b0), "r"(b1));
}
__device__ __forceinline__ uint32_t packhf(float lo, float hi) {
    uint32_t d;
    asm("cvt.rn.f16x2.f32 %0, %1, %2;" : "=r"(d) : "f"(hi), "f"(lo));
    return d;
}
__device__ __forceinline__ uint32_t mul_f16x2(uint32_t a, uint32_t b) {
    uint32_t d; asm("mul.rn.f16x2 %0, %1, %2;" : "=r"(d) : "r"(a), "r"(b)); return d;
}
__device__ __forceinline__ uint32_t fma_f16x2(uint32_t a, uint32_t b, uint32_t c) {
    uint32_t d; asm("fma.rn.f16x2 %0, %1, %2, %3;" : "=r"(d) : "r"(a), "r"(b), "r"(c)); return d;
}
__device__ __forceinline__ uint32_t add_f16x2(uint32_t a, uint32_t b) {
    uint32_t d; asm("add.rn.f16x2 %0, %1, %2;" : "=r"(d) : "r"(a), "r"(b)); return d;
}
__device__ __forceinline__ uint32_t ex2_f16x2(uint32_t a) {
    uint32_t d; asm("ex2.approx.f16x2 %0, %1;" : "=r"(d) : "r"(a)); return d;
}
__device__ __forceinline__ float2 unpack_hf(uint32_t v) {
    __half2 h = *(__half2*)&v; return __half22float2(h);
}

// ---------------------------------------------------------------------------
// Scratch
__device__ float  g_Bn[64 * 512];
__device__ __align__(16) __half g_phiF[64 * 1024];    // phi fp16 [h][m]
__device__ __align__(16) uint32_t g_seqhf[256 * 256]; // seq fp16 [b][512]
__device__ double g_acc;

// ---------------------------------------------------------------------------
__global__ void k_bn(const float* __restrict__ Blog) {
    int h = blockIdx.x, l = threadIdx.x;
    if (h == 0 && l == 0) g_acc = 0.0;
    const float* row = Blog + h * 512;
    float x[16];
    float mx = -3.402823466e38f;
#pragma unroll
    for (int k = 0; k < 16; k++) { x[k] = row[l + k * 32]; mx = fmaxf(mx, x[k]); }
#pragma unroll
    for (int o = 16; o; o >>= 1) mx = fmaxf(mx, __shfl_xor_sync(0xffffffffu, mx, o));
    float s = 0.f;
#pragma unroll
    for (int k = 0; k < 16; k++) { x[k] = exp2f((x[k] - mx) * L2E); s += x[k]; }
#pragma unroll
    for (int o = 16; o; o >>= 1) s += __shfl_xor_sync(0xffffffffu, s, o);
    float inv = 1.0f / s;
#pragma unroll
    for (int k = 0; k < 16; k++) g_Bn[h * 512 + l + k * 32] = x[k] * inv;
}

// phi GEMM + (blocks 0-255) seq fp16 packing
__global__ void k_phi(const float* __restrict__ mem, const float* __restrict__ seq) {
    __shared__ float row[512];
    int m = blockIdx.x, tid = threadIdx.x;
    if (m < 256) {
        int idx = m * 128 + tid;  // 0..32767 float4s
        float4 v = ((const float4*)seq)[idx];
        uint2 o;
        o.x = packhf(v.x, v.y);
        o.y = packhf(v.z, v.w);
        ((uint2*)g_seqhf)[idx] = o;
    }
    for (int i = tid; i < 512; i += 128) row[i] = mem[m * 512 + i];
    __syncthreads();
    int w = tid >> 5, l = tid & 31;
#pragma unroll 4
    for (int hh = 0; hh < 16; hh++) {
        int h = w * 16 + hh;
        float a = 0.f;
#pragma unroll
        for (int k = 0; k < 16; k++) { int i = l + k * 32; a += g_Bn[h * 512 + i] * row[i]; }
#pragma unroll
        for (int o = 16; o; o >>= 1) a += __shfl_xor_sync(0xffffffffu, a, o);
        if (l == 0) g_phiF[h * 1024 + m] = __float2half(a);
    }
}

// ---------------------------------------------------------------------------
// FUSED kernel: hat GEMM (f32 acc) -> Z normalize -> A-frag conversion ->
// score GEMM (f16 acc) -> f16x2 exp epilogue -> BCE.
#define SM_RED   0
#define SM_INVZ  256
#define SM_PLUS  512
#define SM_DYN   2560
// hat buffers: W [32i][64h] fp16 pitch 144 (4608B); S [256b][32i] fp16 pitch 80 (20480B)
#define HB_W 0
#define HB_S 4608
#define HB_STRIDE 25088
// score buffers: PH [64h][128m] fp16 pitch 272 (17408B)
#define PB_STRIDE 17408
#define SM_TOTAL (SM_DYN + 2 * HB_STRIDE)

struct HatSt { float4 a0, a1; uint4 s[4]; };

__device__ __forceinline__ void hat_ldg(HatSt& st, const float* __restrict__ Alog,
                                        int n_pos, int hh, int ig, int i0, int tid) {
    const float4* ap = (const float4*)(Alog + (size_t)(n_pos * 64 + hh) * 512 + i0 + ig * 8);
    st.a0 = ap[0]; st.a1 = ap[1];
    const uint4* sp = (const uint4*)g_seqhf + tid * 64 + (i0 >> 3);
#pragma unroll
    for (int u = 0; u < 4; u++) st.s[u] = sp[u];
}

__device__ __forceinline__ void hat_sts(const HatSt& st, char* sm, int buf,
                                        int n_pos, int hh, int ig, int i0, int tid,
                                        float& zpart) {
    char* base = sm + SM_DYN + buf * HB_STRIDE;
    uint4* d = (uint4*)(base + HB_S + tid * 80);
#pragma unroll
    for (int u = 0; u < 4; u++) d[u] = st.s[u];
    float vv[8] = { st.a0.x, st.a0.y, st.a0.z, st.a0.w,
                    st.a1.x, st.a1.y, st.a1.z, st.a1.w };
#pragma unroll
    for (int j = 0; j < 8; j++) {
        int i = i0 + ig * 8 + j;
        float w = (i < n_pos) ? __expf(vv[j]) : 0.f;
        zpart += w;
        *(__half*)(base + HB_W + (ig * 8 + j) * 144 + hh * 2) = __float2half(w);
    }
}

__device__ __forceinline__ void score_ldg(uint4 r4[4], int c, int tid) {
#pragma unroll
    for (int it = 0; it < 4; it++) {
        int idx = it * 256 + tid;
        int r = idx >> 4, q = idx & 15;
        r4[it] = *(const uint4*)(g_phiF + r * 1024 + c * 128 + q * 8);
    }
}
__device__ __forceinline__ void score_sts(const uint4 r4[4], char* sm, int buf, int tid) {
    char* base = sm + SM_DYN + buf * PB_STRIDE;
#pragma unroll
    for (int it = 0; it < 4; it++) {
        int idx = it * 256 + tid;
        int r = idx >> 4, q = idx & 15;
        *(uint4*)(base + r * 272 + q * 16) = r4[it];
    }
}

__global__ void __launch_bounds__(256, 2) k_fused(const float* __restrict__ Alog,
                                                  const float* __restrict__ seq,
                                                  const float* __restrict__ mem) {
    extern __shared__ char sm[];
    int tid = threadIdx.x, wid = tid >> 5, ln = tid & 31;
    int n_idx = 510 - blockIdx.x, n_pos = n_idx + 1;

    float*    red     = (float*)(sm + SM_RED);
    float*    invZ_s  = (float*)(sm + SM_INVZ);
    uint32_t* plus2_s = (uint32_t*)(sm + SM_PLUS);

#pragma unroll
    for (int q = 0; q < 2; q++) {
        int mp = q * 256 + tid;  // m pair 0..511
        float p0 = (mem[(size_t)(2 * mp) * 512 + n_pos] > 0.0f) ? 1.0f : 0.0f;
        float p1 = (mem[(size_t)(2 * mp + 1) * 512 + n_pos] > 0.0f) ? 1.0f : 0.0f;
        plus2_s[mp] = packhf(p0, p1);
    }

    uint32_t dynb = smem_u32(sm + SM_DYN);

    // ============================ HAT PHASE (f32 acc) ============================
    float C[2][8][4];
#pragma unroll
    for (int mi = 0; mi < 2; mi++)
#pragma unroll
        for (int j = 0; j < 8; j++)
#pragma unroll
            for (int q = 0; q < 4; q++) C[mi][j][q] = 0.f;

    int hh = tid >> 2, ig = tid & 3;
    float zpart = 0.f;
    int nch = (n_pos + 31) >> 5;

    HatSt st;
    hat_ldg(st, Alog, n_pos, hh, ig, 0, tid);
    hat_sts(st, sm, 0, n_pos, hh, ig, 0, tid, zpart);
    __syncthreads();
    if (nch > 1) hat_ldg(st, Alog, n_pos, hh, ig, 32, tid);

    for (int kc = 0; kc < nch; kc++) {
        uint32_t Bb = dynb + (kc & 1) * HB_STRIDE;
#pragma unroll
        for (int ks = 0; ks < 2; ks++) {
            uint32_t aS[2][4];
#pragma unroll
            for (int mi = 0; mi < 2; mi++)
                ldsm_x4(aS[mi], Bb + HB_S + (wid * 32 + mi * 16 + (ln & 15)) * 80 +
                                 ks * 32 + (ln >> 4) * 16);
#pragma unroll
            for (int nt = 0; nt < 4; nt++) {
                uint32_t wF[4];
                uint32_t off = (ks * 16 + (ln & 15)) * 144 + (nt * 16 + (ln >> 4) * 8) * 2;
                ldsm_x4t(wF, Bb + HB_W + off);
#pragma unroll
                for (int mi = 0; mi < 2; mi++) {
                    mma_f16(C[mi][nt * 2 + 0], aS[mi], wF[0], wF[1]);
                    mma_f16(C[mi][nt * 2 + 1], aS[mi], wF[2], wF[3]);
                }
            }
        }
        if (kc + 1 < nch)
            hat_sts(st, sm, (kc + 1) & 1, n_pos, hh, ig, (kc + 1) * 32, tid, zpart);
        __syncthreads();
        if (kc + 2 < nch) hat_ldg(st, Alog, n_pos, hh, ig, (kc + 2) * 32, tid);
    }

    // Z reduce (4 lanes per h) and normalize C
    zpart += __shfl_xor_sync(0xffffffffu, zpart, 1);
    zpart += __shfl_xor_sync(0xffffffffu, zpart, 2);
    if ((tid & 3) == 0) invZ_s[hh] = 1.0f / zpart;
    __syncthreads();

#pragma unroll
    for (int j = 0; j < 8; j++) {
        int h0 = j * 8 + 2 * (ln & 3);
        float iz0 = invZ_s[h0], iz1 = invZ_s[h0 + 1];
#pragma unroll
        for (int mi = 0; mi < 2; mi++) {
            C[mi][j][0] *= iz0; C[mi][j][1] *= iz1;
            C[mi][j][2] *= iz0; C[mi][j][3] *= iz1;
        }
    }

    // ================= CONVERT hat C-frags -> score A-frags (fp16) =========
    uint32_t aF[2][4][4];
#pragma unroll
    for (int mi = 0; mi < 2; mi++) {
#pragma unroll
        for (int kj = 0; kj < 4; kj++) {
            const float* t0 = C[mi][2 * kj];
            const float* t1 = C[mi][2 * kj + 1];
            aF[mi][kj][0] = packhf(t0[0], t0[1]);
            aF[mi][kj][1] = packhf(t0[2], t0[3]);
            aF[mi][kj][2] = packhf(t1[0], t1[1]);
            aF[mi][kj][3] = packhf(t1[2], t1[3]);
        }
    }

    // =================== SCORE PHASE (f16 acc + f16x2 epilogue) ============
    float num[2][2] = {{0.f, 0.f}, {0.f, 0.f}};
    float den[2][2] = {{0.f, 0.f}, {0.f, 0.f}};

    uint4 r4[4];
    score_ldg(r4, 0, tid);
    score_sts(r4, sm, 0, tid);
    __syncthreads();
    score_ldg(r4, 1, tid);

    for (int c = 0; c < 8; c++) {
        uint32_t Pb = dynb + (c & 1) * PB_STRIDE;
        uint32_t num2[2][2] = {{0u, 0u}, {0u, 0u}};
        uint32_t den2[2][2] = {{0u, 0u}, {0u, 0u}};
#pragma unroll
        for (int pr = 0; pr < 8; pr++) {
            uint32_t cc[2][2][2];
#pragma unroll
            for (int mi = 0; mi < 2; mi++)
#pragma unroll
                for (int t2 = 0; t2 < 2; t2++) { cc[mi][t2][0] = 0u; cc[mi][t2][1] = 0u; }

#pragma unroll
            for (int kj = 0; kj < 4; kj++) {
                uint32_t bF[4];
                uint32_t off = (kj * 16 + (ln & 15)) * 272 + (pr * 16 + (ln >> 4) * 8) * 2;
                ldsm_x4t(bF, Pb + off);
#pragma unroll
                for (int mi = 0; mi < 2; mi++) {
                    mma_f16acc(cc[mi][0], aF[mi][kj], bF[0], bF[1]);
                    mma_f16acc(cc[mi][1], aF[mi][kj], bF[2], bF[3]);
                }
            }
#pragma unroll
            for (int t2 = 0; t2 < 2; t2++) {
                uint32_t p2 = plus2_s[c * 64 + pr * 8 + t2 * 4 + (ln & 3)];
#pragma unroll
                for (int mi = 0; mi < 2; mi++) {
#pragma unroll
                    for (int r2 = 0; r2 < 2; r2++) {
                        uint32_t e = ex2_f16x2(mul_f16x2(cc[mi][t2][r2], L2E2));
                        den2[mi][r2] = add_f16x2(den2[mi][r2], e);
                        num2[mi][r2] = fma_f16x2(e, p2, num2[mi][r2]);
                    }
                }
            }
        }
        // flush f16x2 chunk accumulators to f32
#pragma unroll
        for (int mi = 0; mi < 2; mi++) {
#pragma unroll
            for (int r2 = 0; r2 < 2; r2++) {
                float2 dd = unpack_hf(den2[mi][r2]);
                float2 nn = unpack_hf(num2[mi][r2]);
                den[mi][r2] += dd.x + dd.y;
                num[mi][r2] += nn.x + nn.y;
            }
        }
        if (c + 1 < 8) score_sts(r4, sm, (c + 1) & 1, tid);
        __syncthreads();
        if (c + 2 < 8) score_ldg(r4, c + 2, tid);
    }

    // reduce over the 4 lanes sharing each row
#pragma unroll
    for (int o = 1; o <= 2; o <<= 1) {
#pragma unroll
        for (int mi = 0; mi < 2; mi++)
#pragma unroll
            for (int ri = 0; ri < 2; ri++) {
                num[mi][ri] += __shfl_xor_sync(0xffffffffu, num[mi][ri], o);
                den[mi][ri] += __shfl_xor_sync(0xffffffffu, den[mi][ri], o);
            }
    }
    if ((ln & 3) == 0) {
        int r = ln >> 2;
        float bce = 0.f;
#pragma unroll
        for (int mi = 0; mi < 2; mi++) {
#pragma unroll
            for (int ri = 0; ri < 2; ri++) {
                int b = wid * 32 + mi * 16 + ri * 8 + r;
                float prob = num[mi][ri] / den[mi][ri];
                prob = fminf(fmaxf(prob, 1e-6f), 1.0f - 1e-6f);
                bool t = seq[b * 512 + n_pos] > 0.0f;
                bce += t ? -logf(prob) : -log1pf(-prob);
            }
        }
        red[wid * 8 + r] = bce;
    }
    __syncthreads();
    if (tid == 0) {
        double s = 0.0;
#pragma unroll
        for (int i = 0; i < 64; i++) s += (double)red[i];
        atomicAdd(&g_acc, s);
    }
}

__global__ void k_final(float* out) {
    out[0] = (float)(g_acc * (1.0 / (256.0 * 511.0)));
}

// ---------------------------------------------------------------------------
extern "C" void kernel_launch(void* const* d_in, const int* in_sizes, int n_in,
                              void* d_out, int out_size) {
    const float *seq = 0, *mem = 0, *Al = 0, *Bl = 0;
    for (int i = 0; i < n_in; i++) {
        switch (in_sizes[i]) {
            case 131072:   seq = (const float*)d_in[i]; break;  // (256,512)
            case 524288:   mem = (const float*)d_in[i]; break;  // (1024,512)
            case 16777216: Al  = (const float*)d_in[i]; break;  // (512,64,512)
            case 32768:    Bl  = (const float*)d_in[i]; break;  // (64,512)
        }
    }
    if (!seq) seq = (const float*)d_in[0];
    if (!mem) mem = (const float*)d_in[1];
    if (!Al)  Al  = (const float*)d_in[2];
    if (!Bl)  Bl  = (const float*)d_in[3];

    cudaFuncSetAttribute(k_fused, cudaFuncAttributeMaxDynamicSharedMemorySize, SM_TOTAL);

    k_bn<<<64, 32>>>(Bl);
    k_phi<<<1024, 128>>>(mem, seq);
    k_fused<<<511, 256, SM_TOTAL>>>(Al, seq, mem);
    k_final<<<1, 1>>>((float*)d_out);
}